// round 1
// baseline (speedup 1.0000x reference)
#include <cuda_runtime.h>
#include <cuda_bf16.h>
#include <math.h>

// ---------------------------------------------------------------------------
// Problem constants
// ---------------------------------------------------------------------------
#define BB   512          // batch
#define HH   128
#define WW   128
#define CONVN 16129       // 127*127
#define DIM  4096
#define OUTN (BB * DIM)   // 2097152

// ---------------------------------------------------------------------------
// Scratch (no cudaMalloc allowed -> __device__ globals)
// ---------------------------------------------------------------------------
__device__ float g_c[BB];                 // conv_out
__device__ float g_a[BB];                 // attn_out
__device__ float g_act1[OUTN];
__device__ float g_act2[OUTN];
__device__ float g_act3[OUTN];
#define FID_BLOCKS 512
__device__ double g_partials[FID_BLOCKS * 10];

// ---------------------------------------------------------------------------
// Packed f32x2 helpers (sm_100+: fma.rn.f32x2 doubles fp32 FMA throughput)
// ---------------------------------------------------------------------------
__device__ __forceinline__ unsigned long long pk2(float lo, float hi) {
    unsigned long long r;
    asm("mov.b64 %0, {%1, %2};" : "=l"(r) : "f"(lo), "f"(hi));
    return r;
}
__device__ __forceinline__ void upk2(unsigned long long v, float& lo, float& hi) {
    asm("mov.b64 {%0, %1}, %2;" : "=f"(lo), "=f"(hi) : "l"(v));
}
__device__ __forceinline__ void ffma2(unsigned long long& d,
                                      unsigned long long a,
                                      unsigned long long b) {
    asm("fma.rn.f32x2 %0, %1, %2, %3;" : "=l"(d) : "l"(a), "l"(b), "l"(d));
}

// ---------------------------------------------------------------------------
// 1) Conv 2x2 valid + bias + sigmoid + mean  -> g_c[n]
//    One block per image, 256 threads.
// ---------------------------------------------------------------------------
__global__ void conv_kernel(const float* __restrict__ x,
                            const float* __restrict__ cw,
                            const float* __restrict__ cb,
                            float* __restrict__ cOut) {
    const int n = blockIdx.x;
    const float* xp = x + n * HH * WW;
    const float w00 = cw[0], w01 = cw[1], w10 = cw[2], w11 = cw[3];
    const float bias = cb[0];
    float s = 0.0f;
    for (int idx = threadIdx.x; idx < CONVN; idx += 256) {
        int i = idx / 127;
        int j = idx - i * 127;
        const float* r0 = xp + i * WW + j;
        float v = r0[0] * w00 + r0[1] * w01 + r0[WW] * w10 + r0[WW + 1] * w11 + bias;
        s += 1.0f / (1.0f + expf(-v));
    }
    __shared__ float red[256];
    red[threadIdx.x] = s;
    __syncthreads();
    #pragma unroll
    for (int off = 128; off > 0; off >>= 1) {
        if (threadIdx.x < off) red[threadIdx.x] += red[threadIdx.x + off];
        __syncthreads();
    }
    if (threadIdx.x == 0) cOut[n] = red[0] / (float)CONVN;
}

// ---------------------------------------------------------------------------
// 2) Scalar attention (EMBED_DIM = 1)   -> g_a[i]
// ---------------------------------------------------------------------------
__global__ void attn_kernel(const float* __restrict__ c,
                            const float* __restrict__ rot,
                            const float* __restrict__ ent,
                            float* __restrict__ a) {
    __shared__ float cs[BB];
    const int t = threadIdx.x;
    cs[t] = c[t];
    __syncthreads();
    const float r = rot[0], e = ent[0];
    const float qi = cs[t] * r;
    float m = -3.4e38f;
    for (int j = 0; j < BB; j++) m = fmaxf(m, qi * (cs[j] * e));
    float se = 0.0f, sa = 0.0f;
    for (int j = 0; j < BB; j++) {
        float ex = expf(qi * (cs[j] * e) - m);
        se += ex;
        sa += ex * cs[j];
    }
    a[t] = sa / se;
}

// ---------------------------------------------------------------------------
// 3) Layer 1 (rank-1): out[i,j] = tanh(a_i * W1[j] + b1[j])
// ---------------------------------------------------------------------------
__global__ void layer1_kernel(const float* __restrict__ a,
                              const float* __restrict__ W1,
                              const float* __restrict__ b1,
                              float* __restrict__ out) {
    int idx = blockIdx.x * 256 + threadIdx.x;
    int i = idx >> 12;
    int j = idx & (DIM - 1);
    out[idx] = tanhf(fmaf(a[i], W1[j], b1[j]));
}

// ---------------------------------------------------------------------------
// 4) GEMM + bias + tanh:  C[512,4096] = tanh(A[512,4096] @ W[4096,4096]^T + b)
//    128x128x16 tiles, 256 threads, 8x8 microtile, f32x2 packed FMA,
//    double-buffered shared memory.
// ---------------------------------------------------------------------------
#define GBK 16
#define SSTR 132   // padded row stride (16B-aligned, halves STS conflicts)

__global__ void __launch_bounds__(256, 1)
gemm_tanh_kernel(const float* __restrict__ A, const float* __restrict__ W,
                 const float* __restrict__ bias, float* __restrict__ C) {
    constexpr int K = DIM;
    __shared__ float As[2][GBK * SSTR];
    __shared__ float Bs[2][GBK * SSTR];

    const int t = threadIdx.x;
    const int tx = t & 15;   // n direction
    const int ty = t >> 4;   // m direction
    const int m0 = blockIdx.y * 128;
    const int n0 = blockIdx.x * 128;

    const int lr = t >> 2;          // load row 0..63
    const int lk = (t & 3) * 4;     // k sub-offset 0,4,8,12

    const float* Ag = A + (size_t)(m0 + lr) * K + lk;
    const float* Bg = W + (size_t)(n0 + lr) * K + lk;

    unsigned long long acc[8][4];
    #pragma unroll
    for (int i = 0; i < 8; i++)
        #pragma unroll
        for (int j = 0; j < 4; j++) acc[i][j] = 0ULL;

    float4 pa0, pa1, pb0, pb1;

    // preload tile 0
    pa0 = *(const float4*)(Ag);
    pa1 = *(const float4*)(Ag + (size_t)64 * K);
    pb0 = *(const float4*)(Bg);
    pb1 = *(const float4*)(Bg + (size_t)64 * K);
    {
        float* as = As[0]; float* bs = Bs[0];
        as[(lk + 0) * SSTR + lr] = pa0.x; as[(lk + 1) * SSTR + lr] = pa0.y;
        as[(lk + 2) * SSTR + lr] = pa0.z; as[(lk + 3) * SSTR + lr] = pa0.w;
        as[(lk + 0) * SSTR + lr + 64] = pa1.x; as[(lk + 1) * SSTR + lr + 64] = pa1.y;
        as[(lk + 2) * SSTR + lr + 64] = pa1.z; as[(lk + 3) * SSTR + lr + 64] = pa1.w;
        bs[(lk + 0) * SSTR + lr] = pb0.x; bs[(lk + 1) * SSTR + lr] = pb0.y;
        bs[(lk + 2) * SSTR + lr] = pb0.z; bs[(lk + 3) * SSTR + lr] = pb0.w;
        bs[(lk + 0) * SSTR + lr + 64] = pb1.x; bs[(lk + 1) * SSTR + lr + 64] = pb1.y;
        bs[(lk + 2) * SSTR + lr + 64] = pb1.z; bs[(lk + 3) * SSTR + lr + 64] = pb1.w;
    }
    __syncthreads();

    const int NT = K / GBK;   // 256
    for (int kt = 0; kt < NT; kt++) {
        const int buf = kt & 1;
        if (kt + 1 < NT) {
            const float* Ag2 = Ag + (kt + 1) * GBK;
            const float* Bg2 = Bg + (kt + 1) * GBK;
            pa0 = *(const float4*)(Ag2);
            pa1 = *(const float4*)(Ag2 + (size_t)64 * K);
            pb0 = *(const float4*)(Bg2);
            pb1 = *(const float4*)(Bg2 + (size_t)64 * K);
        }
        const float* as = As[buf];
        const float* bs = Bs[buf];
        #pragma unroll
        for (int k = 0; k < GBK; k++) {
            float4 av0 = *(const float4*)(as + k * SSTR + ty * 8);
            float4 av1 = *(const float4*)(as + k * SSTR + ty * 8 + 4);
            ulonglong2 bv0 = *(const ulonglong2*)(bs + k * SSTR + tx * 8);
            ulonglong2 bv1 = *(const ulonglong2*)(bs + k * SSTR + tx * 8 + 4);
            unsigned long long bb[4] = {bv0.x, bv0.y, bv1.x, bv1.y};
            float aarr[8] = {av0.x, av0.y, av0.z, av0.w,
                             av1.x, av1.y, av1.z, av1.w};
            #pragma unroll
            for (int mi = 0; mi < 8; mi++) {
                unsigned long long ad = pk2(aarr[mi], aarr[mi]);
                #pragma unroll
                for (int nj = 0; nj < 4; nj++) ffma2(acc[mi][nj], ad, bb[nj]);
            }
        }
        if (kt + 1 < NT) {
            float* as2 = As[buf ^ 1]; float* bs2 = Bs[buf ^ 1];
            as2[(lk + 0) * SSTR + lr] = pa0.x; as2[(lk + 1) * SSTR + lr] = pa0.y;
            as2[(lk + 2) * SSTR + lr] = pa0.z; as2[(lk + 3) * SSTR + lr] = pa0.w;
            as2[(lk + 0) * SSTR + lr + 64] = pa1.x; as2[(lk + 1) * SSTR + lr + 64] = pa1.y;
            as2[(lk + 2) * SSTR + lr + 64] = pa1.z; as2[(lk + 3) * SSTR + lr + 64] = pa1.w;
            bs2[(lk + 0) * SSTR + lr] = pb0.x; bs2[(lk + 1) * SSTR + lr] = pb0.y;
            bs2[(lk + 2) * SSTR + lr] = pb0.z; bs2[(lk + 3) * SSTR + lr] = pb0.w;
            bs2[(lk + 0) * SSTR + lr + 64] = pb1.x; bs2[(lk + 1) * SSTR + lr + 64] = pb1.y;
            bs2[(lk + 2) * SSTR + lr + 64] = pb1.z; bs2[(lk + 3) * SSTR + lr + 64] = pb1.w;
        }
        __syncthreads();
    }

    // epilogue: bias + tanh, vectorized stores
    float bn[8];
    #pragma unroll
    for (int nj = 0; nj < 8; nj++) bn[nj] = bias[n0 + tx * 8 + nj];
    #pragma unroll
    for (int mi = 0; mi < 8; mi++) {
        float o[8];
        #pragma unroll
        for (int p = 0; p < 4; p++) {
            float lo, hi;
            upk2(acc[mi][p], lo, hi);
            o[2 * p] = lo; o[2 * p + 1] = hi;
        }
        #pragma unroll
        for (int nj = 0; nj < 8; nj++) o[nj] = tanhf(o[nj] + bn[nj]);
        float4* dst = (float4*)(C + (size_t)(m0 + ty * 8 + mi) * DIM + n0 + tx * 8);
        dst[0] = make_float4(o[0], o[1], o[2], o[3]);
        dst[1] = make_float4(o[4], o[5], o[6], o[7]);
    }
}

// ---------------------------------------------------------------------------
// 5) Fidelity dots: 10 unique <S_i, S_j> over 2M elems, deterministic 2-stage
// ---------------------------------------------------------------------------
__global__ void fid_kernel(const float* __restrict__ a1, const float* __restrict__ a2,
                           const float* __restrict__ a3, const float* __restrict__ a4) {
    double s[10];
    #pragma unroll
    for (int k = 0; k < 10; k++) s[k] = 0.0;
    const int stride = gridDim.x * blockDim.x;
    for (int idx = blockIdx.x * blockDim.x + threadIdx.x; idx < OUTN; idx += stride) {
        double v1 = (double)a1[idx], v2 = (double)a2[idx];
        double v3 = (double)a3[idx], v4 = (double)a4[idx];
        s[0] += v1 * v1; s[1] += v1 * v2; s[2] += v1 * v3; s[3] += v1 * v4;
        s[4] += v2 * v2; s[5] += v2 * v3; s[6] += v2 * v4;
        s[7] += v3 * v3; s[8] += v3 * v4;
        s[9] += v4 * v4;
    }
    // warp reduce (fixed tree -> deterministic)
    #pragma unroll
    for (int k = 0; k < 10; k++)
        #pragma unroll
        for (int off = 16; off > 0; off >>= 1)
            s[k] += __shfl_down_sync(0xFFFFFFFFu, s[k], off);
    __shared__ double ws[8][10];
    const int wid = threadIdx.x >> 5, lid = threadIdx.x & 31;
    if (lid == 0)
        #pragma unroll
        for (int k = 0; k < 10; k++) ws[wid][k] = s[k];
    __syncthreads();
    if (threadIdx.x == 0) {
        #pragma unroll
        for (int k = 0; k < 10; k++) {
            double acc = 0.0;
            for (int w = 0; w < 8; w++) acc += ws[w][k];
            g_partials[blockIdx.x * 10 + k] = acc;
        }
    }
}

// 6) finalize: sum partials (fixed order) -> fid -> threshold -> weights
__global__ void finalize_kernel(float* __restrict__ wout) {
    __shared__ double dots[10];
    const int t = threadIdx.x;
    const int w = t >> 5, lid = t & 31;
    if (w < 10) {
        double acc = 0.0;
        for (int p = lid; p < FID_BLOCKS; p += 32) acc += g_partials[p * 10 + w];
        #pragma unroll
        for (int off = 16; off > 0; off >>= 1)
            acc += __shfl_down_sync(0xFFFFFFFFu, acc, off);
        if (lid == 0) dots[w] = acc;
    }
    __syncthreads();
    if (t < 16) {
        int i = t >> 2, j = t & 3;
        // flat index for (min,max) pair in upper-triangular order
        int ii = i < j ? i : j, jj = i < j ? j : i;
        const int base[4] = {0, 4, 7, 9};
        double dij = dots[base[ii] + (jj - ii)];
        double dii = dots[base[ii]];
        double djj = dots[base[jj]];
        double ni = sqrt(dii) + 1e-12;
        double nj = sqrt(djj) + 1e-12;
        double sh = dij / (ni * nj);
        double fid = sh * sh;
        float val = (fid >= 0.8 && i != j) ? 1.0f : 0.0f;
        wout[t] = val;
    }
}

// ---------------------------------------------------------------------------
// kernel_launch
//   inputs: x, conv_w, conv_b, rotation, entangle, W1,b1, W2,b2, W3,b3, W4,b4
//   output: [out(512*4096) | weights(16)] as float32
// ---------------------------------------------------------------------------
extern "C" void kernel_launch(void* const* d_in, const int* in_sizes, int n_in,
                              void* d_out, int out_size) {
    const float* x    = (const float*)d_in[0];
    const float* cw   = (const float*)d_in[1];
    const float* cb   = (const float*)d_in[2];
    const float* rot  = (const float*)d_in[3];
    const float* ent  = (const float*)d_in[4];
    const float* W1   = (const float*)d_in[5];
    const float* b1   = (const float*)d_in[6];
    const float* W2   = (const float*)d_in[7];
    const float* b2   = (const float*)d_in[8];
    const float* W3   = (const float*)d_in[9];
    const float* b3   = (const float*)d_in[10];
    const float* W4   = (const float*)d_in[11];
    const float* b4   = (const float*)d_in[12];
    float* out = (float*)d_out;

    float *gc, *ga, *ga1, *ga2, *ga3;
    cudaGetSymbolAddress((void**)&gc,  g_c);
    cudaGetSymbolAddress((void**)&ga,  g_a);
    cudaGetSymbolAddress((void**)&ga1, g_act1);
    cudaGetSymbolAddress((void**)&ga2, g_act2);
    cudaGetSymbolAddress((void**)&ga3, g_act3);

    conv_kernel<<<BB, 256>>>(x, cw, cb, gc);
    attn_kernel<<<1, BB>>>(gc, rot, ent, ga);
    layer1_kernel<<<OUTN / 256, 256>>>(ga, W1, b1, ga1);

    dim3 ggrid(DIM / 128, BB / 128);   // (32, 4)
    gemm_tanh_kernel<<<ggrid, 256>>>(ga1, W2, b2, ga2);
    gemm_tanh_kernel<<<ggrid, 256>>>(ga2, W3, b3, ga3);
    gemm_tanh_kernel<<<ggrid, 256>>>(ga3, W4, b4, out);

    fid_kernel<<<FID_BLOCKS, 256>>>(ga1, ga2, ga3, out);
    finalize_kernel<<<1, 320>>>(out + OUTN);
}

// round 3
// speedup vs baseline: 1.4728x; 1.4728x over previous
#include <cuda_runtime.h>
#include <cuda_bf16.h>
#include <math.h>
#include <stdint.h>

// ---------------------------------------------------------------------------
// Problem constants
// ---------------------------------------------------------------------------
#define BB   512
#define HH   128
#define WW   128
#define CONVN 16129
#define DIM  4096
#define KDIM 4096
#define OUTN (BB * DIM)

// ---------------------------------------------------------------------------
// Scratch (__device__ globals; no cudaMalloc allowed)
// ---------------------------------------------------------------------------
__device__ float g_c[BB];
__device__ float g_a[BB];
__device__ float g_act1[OUTN];
__device__ float g_act2[OUTN];
__device__ float g_act3[OUTN];
__device__ __nv_bfloat16 g_ahi[3][OUTN];
__device__ __nv_bfloat16 g_alo[3][OUTN];
__device__ __nv_bfloat16 g_whi[3][DIM * KDIM];
__device__ __nv_bfloat16 g_wlo[3][DIM * KDIM];
#define FID_BLOCKS 512
__device__ double g_partials[FID_BLOCKS * 10];

// ---------------------------------------------------------------------------
// PTX helpers (all plain-PTX, valid on non-'a' targets)
// ---------------------------------------------------------------------------
__device__ __forceinline__ uint32_t smem_to_u32(const void* p) {
    uint32_t a;
    asm("{ .reg .u64 t; cvta.to.shared.u64 t, %1; cvt.u32.u64 %0, t; }"
        : "=r"(a) : "l"(p));
    return a;
}
__device__ __forceinline__ void cpasync16(uint32_t dst, const void* gsrc) {
    asm volatile("cp.async.cg.shared.global [%0], [%1], 16;"
                 :: "r"(dst), "l"(__cvta_generic_to_global(gsrc)) : "memory");
}
#define CP_COMMIT() asm volatile("cp.async.commit_group;" ::: "memory")
template <int N>
__device__ __forceinline__ void cp_wait() {
    asm volatile("cp.async.wait_group %0;" :: "n"(N) : "memory");
}
__device__ __forceinline__ void ldsm_x4(uint32_t r[4], uint32_t addr) {
    asm volatile("ldmatrix.sync.aligned.m8n8.x4.shared.b16 {%0,%1,%2,%3}, [%4];"
                 : "=r"(r[0]), "=r"(r[1]), "=r"(r[2]), "=r"(r[3]) : "r"(addr));
}
__device__ __forceinline__ void mma16816(float d[4], const uint32_t a[4],
                                         uint32_t b0, uint32_t b1) {
    asm volatile(
        "mma.sync.aligned.m16n8k16.row.col.f32.bf16.bf16.f32 "
        "{%0,%1,%2,%3}, {%4,%5,%6,%7}, {%8,%9}, {%0,%1,%2,%3};"
        : "+f"(d[0]), "+f"(d[1]), "+f"(d[2]), "+f"(d[3])
        : "r"(a[0]), "r"(a[1]), "r"(a[2]), "r"(a[3]), "r"(b0), "r"(b1));
}

// ---------------------------------------------------------------------------
// 1) Conv 2x2 valid + bias + sigmoid + mean  -> g_c[n]
// ---------------------------------------------------------------------------
__global__ void conv_kernel(const float* __restrict__ x,
                            const float* __restrict__ cw,
                            const float* __restrict__ cb,
                            float* __restrict__ cOut) {
    const int n = blockIdx.x;
    const float* xp = x + n * HH * WW;
    const float w00 = cw[0], w01 = cw[1], w10 = cw[2], w11 = cw[3];
    const float bias = cb[0];
    float s = 0.0f;
    for (int idx = threadIdx.x; idx < CONVN; idx += 256) {
        int i = idx / 127;
        int j = idx - i * 127;
        const float* r0 = xp + i * WW + j;
        float v = r0[0] * w00 + r0[1] * w01 + r0[WW] * w10 + r0[WW + 1] * w11 + bias;
        s += 1.0f / (1.0f + expf(-v));
    }
    __shared__ float red[256];
    red[threadIdx.x] = s;
    __syncthreads();
    #pragma unroll
    for (int off = 128; off > 0; off >>= 1) {
        if (threadIdx.x < off) red[threadIdx.x] += red[threadIdx.x + off];
        __syncthreads();
    }
    if (threadIdx.x == 0) cOut[n] = red[0] / (float)CONVN;
}

// ---------------------------------------------------------------------------
// 2) Scalar attention (EMBED_DIM = 1)
// ---------------------------------------------------------------------------
__global__ void attn_kernel(const float* __restrict__ c,
                            const float* __restrict__ rot,
                            const float* __restrict__ ent,
                            float* __restrict__ a) {
    __shared__ float cs[BB];
    const int t = threadIdx.x;
    cs[t] = c[t];
    __syncthreads();
    const float r = rot[0], e = ent[0];
    const float qi = cs[t] * r;
    float m = -3.4e38f;
    for (int j = 0; j < BB; j++) m = fmaxf(m, qi * (cs[j] * e));
    float se = 0.0f, sa = 0.0f;
    for (int j = 0; j < BB; j++) {
        float ex = expf(qi * (cs[j] * e) - m);
        se += ex;
        sa += ex * cs[j];
    }
    a[t] = sa / se;
}

// ---------------------------------------------------------------------------
// 3) Layer 1 (rank-1): act = tanh(a_i * W1[j] + b1[j]); fp32 + bf16 hi/lo
// ---------------------------------------------------------------------------
__global__ void layer1_kernel(const float* __restrict__ a,
                              const float* __restrict__ W1,
                              const float* __restrict__ b1,
                              float* __restrict__ out,
                              __nv_bfloat16* __restrict__ ohi,
                              __nv_bfloat16* __restrict__ olo) {
    int idx = blockIdx.x * 256 + threadIdx.x;
    int i = idx >> 12;
    int j = idx & (DIM - 1);
    float o = tanhf(fmaf(a[i], W1[j], b1[j]));
    out[idx] = o;
    __nv_bfloat16 h = __float2bfloat16(o);
    ohi[idx] = h;
    olo[idx] = __float2bfloat16(o - __bfloat162float(h));
}

// ---------------------------------------------------------------------------
// W -> bf16 hi/lo conversion
// ---------------------------------------------------------------------------
__global__ void convert_w_kernel(const float* __restrict__ W,
                                 __nv_bfloat16* __restrict__ hi,
                                 __nv_bfloat16* __restrict__ lo) {
    int i = (blockIdx.x * 256 + threadIdx.x) * 4;
    float4 v = *(const float4*)(W + i);
    __nv_bfloat16 h0 = __float2bfloat16(v.x);
    __nv_bfloat16 h1 = __float2bfloat16(v.y);
    __nv_bfloat16 h2 = __float2bfloat16(v.z);
    __nv_bfloat16 h3 = __float2bfloat16(v.w);
    __nv_bfloat162 hp0, hp1;
    hp0.x = h0; hp0.y = h1; hp1.x = h2; hp1.y = h3;
    *(__nv_bfloat162*)(hi + i) = hp0;
    *(__nv_bfloat162*)(hi + i + 2) = hp1;
    __nv_bfloat162 lp0, lp1;
    lp0.x = __float2bfloat16(v.x - __bfloat162float(h0));
    lp0.y = __float2bfloat16(v.y - __bfloat162float(h1));
    lp1.x = __float2bfloat16(v.z - __bfloat162float(h2));
    lp1.y = __float2bfloat16(v.w - __bfloat162float(h3));
    *(__nv_bfloat162*)(lo + i) = lp0;
    *(__nv_bfloat162*)(lo + i + 2) = lp1;
}

// ---------------------------------------------------------------------------
// 4) HMMA GEMM + bias + tanh:
//    C[512,4096] = tanh(A @ W^T + b), A/W as bf16 hi/lo; 3-product fp32 recon.
//    CTA tile 128x128, 8 warps (2x4), warp tile 64x32, KT=32, 4-stage cp.async.
// ---------------------------------------------------------------------------
#define KT      32
#define NT      (KDIM / KT)           // 128
#define SROW    40                    // padded row stride in bf16 (80 B)
#define MAT_B   (128 * SROW * 2)      // 10240 B per matrix tile
#define STAGE_B (4 * MAT_B)           // Ahi, Alo, Whi, Wlo
#define NSTAGE  4
#define BIAS_OFF (NSTAGE * STAGE_B)   // 163840
#define SMEM_REQ (BIAS_OFF + 512)

__global__ void __launch_bounds__(256, 1)
gemm_mma_kernel(const __nv_bfloat16* __restrict__ Ahi, const __nv_bfloat16* __restrict__ Alo,
                const __nv_bfloat16* __restrict__ Whi, const __nv_bfloat16* __restrict__ Wlo,
                const float* __restrict__ bias,
                float* __restrict__ C,
                __nv_bfloat16* __restrict__ Chi, __nv_bfloat16* __restrict__ Clo) {
    extern __shared__ __align__(16) char smem[];
    const uint32_t sbase = smem_to_u32(smem);
    float* biasS = (float*)(smem + BIAS_OFF);

    const int t = threadIdx.x;
    const int lane = t & 31;
    const int warp = t >> 5;
    const int mw = warp >> 2;           // 0..1
    const int nw = warp & 3;            // 0..3
    const int M0 = mw * 64;
    const int N0 = nw * 32;
    const int m0 = blockIdx.y * 128;
    const int n0 = blockIdx.x * 128;

    if (t < 128) biasS[t] = bias[n0 + t];

    // ----- producer mapping: 4 matrices x 128 rows x 4 x 16B chunks -----
    const int mat = t >> 6;            // 0..3
    const int rr  = (t & 63) * 2;      // base row (2 rows per thread)
    const __nv_bfloat16* gsrc0;
    if (mat == 0)      gsrc0 = Ahi + (size_t)m0 * KDIM;
    else if (mat == 1) gsrc0 = Alo + (size_t)m0 * KDIM;
    else if (mat == 2) gsrc0 = Whi + (size_t)n0 * KDIM;
    else               gsrc0 = Wlo + (size_t)n0 * KDIM;

    #define ISSUE_STAGE(ktv) do {                                              \
        const int _kt = (ktv);                                                 \
        const uint32_t _stg = sbase + (uint32_t)(_kt & 3) * STAGE_B            \
                            + (uint32_t)mat * MAT_B;                           \
        _Pragma("unroll")                                                      \
        for (int _c = 0; _c < 8; _c++) {                                       \
            const int _r = rr + (_c >> 2);                                     \
            const int _cc = _c & 3;                                            \
            cpasync16(_stg + (uint32_t)(_r * SROW + _cc * 8) * 2,              \
                      gsrc0 + (size_t)_r * KDIM + _kt * KT + _cc * 8);         \
        }                                                                      \
    } while (0)

    // preload stages 0..NSTAGE-2
    #pragma unroll
    for (int s = 0; s < NSTAGE - 1; s++) { ISSUE_STAGE(s); CP_COMMIT(); }

    // ----- ldmatrix lane addressing (constant parts) -----
    const int g = lane >> 3, rin = lane & 7;
    const int rowA = M0 + (g & 1) * 8 + rin;    // + mi*16
    const int colA = (g >> 1) * 8;              // + kc
    const int rowB = N0 + (g >> 1) * 8 + rin;   // + j*16
    const int colB = (g & 1) * 8;               // + kc

    float acc[4][4][4];
    #pragma unroll
    for (int i = 0; i < 4; i++)
        #pragma unroll
        for (int j = 0; j < 4; j++)
            #pragma unroll
            for (int k = 0; k < 4; k++) acc[i][j][k] = 0.0f;

    for (int kt = 0; kt < NT; kt++) {
        cp_wait<NSTAGE - 2>();
        __syncthreads();
        if (kt + NSTAGE - 1 < NT) ISSUE_STAGE(kt + NSTAGE - 1);
        CP_COMMIT();

        const uint32_t stg = sbase + (uint32_t)(kt & 3) * STAGE_B;
        const uint32_t bAh = stg;
        const uint32_t bAl = stg + MAT_B;
        const uint32_t bWh = stg + 2 * MAT_B;
        const uint32_t bWl = stg + 3 * MAT_B;

        #pragma unroll
        for (int h = 0; h < 2; h++) {
            const int kc = h * 16;
            uint32_t ah[4][4], al[4][4];
            #pragma unroll
            for (int mi = 0; mi < 4; mi++) {
                const uint32_t off = (uint32_t)((rowA + mi * 16) * SROW + kc + colA) * 2;
                ldsm_x4(ah[mi], bAh + off);
                ldsm_x4(al[mi], bAl + off);
            }
            uint32_t bh[2][4], bl[2][4];
            #pragma unroll
            for (int j = 0; j < 2; j++) {
                const uint32_t off = (uint32_t)((rowB + j * 16) * SROW + kc + colB) * 2;
                ldsm_x4(bh[j], bWh + off);
                ldsm_x4(bl[j], bWl + off);
            }
            #pragma unroll
            for (int mi = 0; mi < 4; mi++) {
                #pragma unroll
                for (int nj = 0; nj < 4; nj++) {
                    const int jj = nj >> 1, pp = (nj & 1) * 2;
                    mma16816(acc[mi][nj], ah[mi], bh[jj][pp], bh[jj][pp + 1]);
                    mma16816(acc[mi][nj], ah[mi], bl[jj][pp], bl[jj][pp + 1]);
                    mma16816(acc[mi][nj], al[mi], bh[jj][pp], bh[jj][pp + 1]);
                }
            }
        }
    }

    // ----- epilogue: bias + tanh -> fp32 C and bf16 hi/lo -----
    const int r0l = lane >> 2;
    const int c0l = 2 * (lane & 3);
    #pragma unroll
    for (int mi = 0; mi < 4; mi++) {
        #pragma unroll
        for (int nj = 0; nj < 4; nj++) {
            const int gnl = N0 + nj * 8 + c0l;
            const float b0 = biasS[gnl], b1 = biasS[gnl + 1];
            const int gm0 = m0 + M0 + mi * 16 + r0l;
            float v00 = tanhf(acc[mi][nj][0] + b0);
            float v01 = tanhf(acc[mi][nj][1] + b1);
            float v10 = tanhf(acc[mi][nj][2] + b0);
            float v11 = tanhf(acc[mi][nj][3] + b1);
            float* p0 = C + (size_t)gm0 * DIM + n0 + gnl;
            float* p1 = p0 + (size_t)8 * DIM;
            *(float2*)p0 = make_float2(v00, v01);
            *(float2*)p1 = make_float2(v10, v11);
            if (Chi != nullptr) {
                __nv_bfloat16 h00 = __float2bfloat16(v00);
                __nv_bfloat16 h01 = __float2bfloat16(v01);
                __nv_bfloat16 h10 = __float2bfloat16(v10);
                __nv_bfloat16 h11 = __float2bfloat16(v11);
                __nv_bfloat162 hp0; hp0.x = h00; hp0.y = h01;
                __nv_bfloat162 hp1; hp1.x = h10; hp1.y = h11;
                *(__nv_bfloat162*)(Chi + (size_t)gm0 * DIM + n0 + gnl) = hp0;
                *(__nv_bfloat162*)(Chi + (size_t)(gm0 + 8) * DIM + n0 + gnl) = hp1;
                __nv_bfloat162 lp0, lp1;
                lp0.x = __float2bfloat16(v00 - __bfloat162float(h00));
                lp0.y = __float2bfloat16(v01 - __bfloat162float(h01));
                lp1.x = __float2bfloat16(v10 - __bfloat162float(h10));
                lp1.y = __float2bfloat16(v11 - __bfloat162float(h11));
                *(__nv_bfloat162*)(Clo + (size_t)gm0 * DIM + n0 + gnl) = lp0;
                *(__nv_bfloat162*)(Clo + (size_t)(gm0 + 8) * DIM + n0 + gnl) = lp1;
            }
        }
    }
}

// ---------------------------------------------------------------------------
// 5) Fidelity dots (deterministic 2-stage reduction)
// ---------------------------------------------------------------------------
__global__ void fid_kernel(const float* __restrict__ a1, const float* __restrict__ a2,
                           const float* __restrict__ a3, const float* __restrict__ a4) {
    double s[10];
    #pragma unroll
    for (int k = 0; k < 10; k++) s[k] = 0.0;
    const int stride = gridDim.x * blockDim.x;
    for (int idx = blockIdx.x * blockDim.x + threadIdx.x; idx < OUTN; idx += stride) {
        double v1 = (double)a1[idx], v2 = (double)a2[idx];
        double v3 = (double)a3[idx], v4 = (double)a4[idx];
        s[0] += v1 * v1; s[1] += v1 * v2; s[2] += v1 * v3; s[3] += v1 * v4;
        s[4] += v2 * v2; s[5] += v2 * v3; s[6] += v2 * v4;
        s[7] += v3 * v3; s[8] += v3 * v4;
        s[9] += v4 * v4;
    }
    #pragma unroll
    for (int k = 0; k < 10; k++)
        #pragma unroll
        for (int off = 16; off > 0; off >>= 1)
            s[k] += __shfl_down_sync(0xFFFFFFFFu, s[k], off);
    __shared__ double ws[8][10];
    const int wid = threadIdx.x >> 5, lid = threadIdx.x & 31;
    if (lid == 0)
        #pragma unroll
        for (int k = 0; k < 10; k++) ws[wid][k] = s[k];
    __syncthreads();
    if (threadIdx.x == 0) {
        #pragma unroll
        for (int k = 0; k < 10; k++) {
            double acc = 0.0;
            for (int w = 0; w < 8; w++) acc += ws[w][k];
            g_partials[blockIdx.x * 10 + k] = acc;
        }
    }
}

__global__ void finalize_kernel(float* __restrict__ wout) {
    __shared__ double dots[10];
    const int t = threadIdx.x;
    const int w = t >> 5, lid = t & 31;
    if (w < 10) {
        double acc = 0.0;
        for (int p = lid; p < FID_BLOCKS; p += 32) acc += g_partials[p * 10 + w];
        #pragma unroll
        for (int off = 16; off > 0; off >>= 1)
            acc += __shfl_down_sync(0xFFFFFFFFu, acc, off);
        if (lid == 0) dots[w] = acc;
    }
    __syncthreads();
    if (t < 16) {
        int i = t >> 2, j = t & 3;
        int ii = i < j ? i : j, jj = i < j ? j : i;
        const int base[4] = {0, 4, 7, 9};
        double dij = dots[base[ii] + (jj - ii)];
        double dii = dots[base[ii]];
        double djj = dots[base[jj]];
        double ni = sqrt(dii) + 1e-12;
        double nj = sqrt(djj) + 1e-12;
        double sh = dij / (ni * nj);
        double fid = sh * sh;
        wout[t] = (fid >= 0.8 && i != j) ? 1.0f : 0.0f;
    }
}

// ---------------------------------------------------------------------------
// kernel_launch
// ---------------------------------------------------------------------------
extern "C" void kernel_launch(void* const* d_in, const int* in_sizes, int n_in,
                              void* d_out, int out_size) {
    const float* x   = (const float*)d_in[0];
    const float* cw  = (const float*)d_in[1];
    const float* cb  = (const float*)d_in[2];
    const float* rot = (const float*)d_in[3];
    const float* ent = (const float*)d_in[4];
    const float* W1  = (const float*)d_in[5];
    const float* b1  = (const float*)d_in[6];
    const float* W2  = (const float*)d_in[7];
    const float* b2  = (const float*)d_in[8];
    const float* W3  = (const float*)d_in[9];
    const float* b3  = (const float*)d_in[10];
    const float* W4  = (const float*)d_in[11];
    const float* b4  = (const float*)d_in[12];
    float* out = (float*)d_out;

    float *gc, *ga, *ga1, *ga2, *ga3;
    __nv_bfloat16 *ahi, *alo, *whi, *wlo;
    cudaGetSymbolAddress((void**)&gc,  g_c);
    cudaGetSymbolAddress((void**)&ga,  g_a);
    cudaGetSymbolAddress((void**)&ga1, g_act1);
    cudaGetSymbolAddress((void**)&ga2, g_act2);
    cudaGetSymbolAddress((void**)&ga3, g_act3);
    cudaGetSymbolAddress((void**)&ahi, g_ahi);
    cudaGetSymbolAddress((void**)&alo, g_alo);
    cudaGetSymbolAddress((void**)&whi, g_whi);
    cudaGetSymbolAddress((void**)&wlo, g_wlo);

    cudaFuncSetAttribute(gemm_mma_kernel,
                         cudaFuncAttributeMaxDynamicSharedMemorySize, SMEM_REQ);

    const size_t WN = (size_t)DIM * KDIM;

    convert_w_kernel<<<(int)(WN / 1024), 256>>>(W2, whi + 0 * WN, wlo + 0 * WN);
    convert_w_kernel<<<(int)(WN / 1024), 256>>>(W3, whi + 1 * WN, wlo + 1 * WN);
    convert_w_kernel<<<(int)(WN / 1024), 256>>>(W4, whi + 2 * WN, wlo + 2 * WN);

    conv_kernel<<<BB, 256>>>(x, cw, cb, gc);
    attn_kernel<<<1, BB>>>(gc, rot, ent, ga);
    layer1_kernel<<<OUTN / 256, 256>>>(ga, W1, b1, ga1,
                                       ahi + 0 * (size_t)OUTN, alo + 0 * (size_t)OUTN);

    dim3 ggrid(DIM / 128, BB / 128);  // (32, 4)
    gemm_mma_kernel<<<ggrid, 256, SMEM_REQ>>>(
        ahi + 0 * (size_t)OUTN, alo + 0 * (size_t)OUTN,
        whi + 0 * WN,           wlo + 0 * WN,           b2, ga2,
        ahi + 1 * (size_t)OUTN, alo + 1 * (size_t)OUTN);
    gemm_mma_kernel<<<ggrid, 256, SMEM_REQ>>>(
        ahi + 1 * (size_t)OUTN, alo + 1 * (size_t)OUTN,
        whi + 1 * WN,           wlo + 1 * WN,           b3, ga3,
        ahi + 2 * (size_t)OUTN, alo + 2 * (size_t)OUTN);
    gemm_mma_kernel<<<ggrid, 256, SMEM_REQ>>>(
        ahi + 2 * (size_t)OUTN, alo + 2 * (size_t)OUTN,
        whi + 2 * WN,           wlo + 2 * WN,           b4, out,
        nullptr, nullptr);

    fid_kernel<<<FID_BLOCKS, 256>>>(ga1, ga2, ga3, out);
    finalize_kernel<<<1, 320>>>(out + OUTN);
}

// round 4
// speedup vs baseline: 1.7560x; 1.1923x over previous
#include <cuda_runtime.h>
#include <cuda_bf16.h>
#include <cuda_fp16.h>
#include <math.h>
#include <stdint.h>

// ---------------------------------------------------------------------------
// Problem constants
// ---------------------------------------------------------------------------
#define BB   512
#define HH   128
#define WW   128
#define CONVN 16129
#define DIM  4096
#define KDIM 4096
#define OUTN (BB * DIM)

// ---------------------------------------------------------------------------
// Scratch (__device__ globals; no cudaMalloc allowed)
// ---------------------------------------------------------------------------
__device__ float g_c[BB];
__device__ float g_a[BB];
__device__ float g_act1[OUTN];
__device__ float g_act2[OUTN];
__device__ float g_act3[OUTN];
__device__ __half g_ahi[3][OUTN];
__device__ __half g_alo[3][OUTN];
__device__ __half g_wh[3][DIM * KDIM];
#define FID_BLOCKS 512
__device__ double g_partials[FID_BLOCKS * 10];

// ---------------------------------------------------------------------------
// PTX helpers (plain-PTX, valid on non-'a' targets)
// ---------------------------------------------------------------------------
__device__ __forceinline__ uint32_t smem_to_u32(const void* p) {
    uint32_t a;
    asm("{ .reg .u64 t; cvta.to.shared.u64 t, %1; cvt.u32.u64 %0, t; }"
        : "=r"(a) : "l"(p));
    return a;
}
__device__ __forceinline__ void cpasync16(uint32_t dst, const void* gsrc) {
    asm volatile("cp.async.cg.shared.global [%0], [%1], 16;"
                 :: "r"(dst), "l"(__cvta_generic_to_global(gsrc)) : "memory");
}
#define CP_COMMIT() asm volatile("cp.async.commit_group;" ::: "memory")
template <int N>
__device__ __forceinline__ void cp_wait() {
    asm volatile("cp.async.wait_group %0;" :: "n"(N) : "memory");
}
__device__ __forceinline__ void ldsm_x4(uint32_t r[4], uint32_t addr) {
    asm volatile("ldmatrix.sync.aligned.m8n8.x4.shared.b16 {%0,%1,%2,%3}, [%4];"
                 : "=r"(r[0]), "=r"(r[1]), "=r"(r[2]), "=r"(r[3]) : "r"(addr));
}
__device__ __forceinline__ void mma16816h(float d[4], const uint32_t a[4],
                                          uint32_t b0, uint32_t b1) {
    asm volatile(
        "mma.sync.aligned.m16n8k16.row.col.f32.f16.f16.f32 "
        "{%0,%1,%2,%3}, {%4,%5,%6,%7}, {%8,%9}, {%0,%1,%2,%3};"
        : "+f"(d[0]), "+f"(d[1]), "+f"(d[2]), "+f"(d[3])
        : "r"(a[0]), "r"(a[1]), "r"(a[2]), "r"(a[3]), "r"(b0), "r"(b1));
}

// ---------------------------------------------------------------------------
// 1) Conv 2x2 valid + bias + sigmoid + mean -> g_c[n]  (float4 loads, no idiv)
// ---------------------------------------------------------------------------
__global__ void conv_kernel(const float* __restrict__ x,
                            const float* __restrict__ cw,
                            const float* __restrict__ cb,
                            float* __restrict__ cOut) {
    const int n = blockIdx.x;
    const float* xp = x + n * HH * WW;
    const float w00 = cw[0], w01 = cw[1], w10 = cw[2], w11 = cw[3];
    const float bias = cb[0];
    float s = 0.0f;
    // 127 rows x 32 col-groups of 4
    for (int idx = threadIdx.x; idx < 127 * 32; idx += 256) {
        const int i = idx >> 5;
        const int j = (idx & 31) * 4;
        const float* r0 = xp + i * WW + j;
        const float* r1 = r0 + WW;
        float4 a = *(const float4*)r0;
        float4 b = *(const float4*)r1;
        float a4 = 0.0f, b4 = 0.0f;
        if (j + 4 < WW) { a4 = r0[4]; b4 = r1[4]; }
        float x0[5] = {a.x, a.y, a.z, a.w, a4};
        float x1[5] = {b.x, b.y, b.z, b.w, b4};
        #pragma unroll
        for (int k = 0; k < 4; k++) {
            if (j + k < 127) {
                float v = x0[k] * w00 + x0[k + 1] * w01
                        + x1[k] * w10 + x1[k + 1] * w11 + bias;
                s += 1.0f / (1.0f + __expf(-v));
            }
        }
    }
    __shared__ float red[256];
    red[threadIdx.x] = s;
    __syncthreads();
    #pragma unroll
    for (int off = 128; off > 0; off >>= 1) {
        if (threadIdx.x < off) red[threadIdx.x] += red[threadIdx.x + off];
        __syncthreads();
    }
    if (threadIdx.x == 0) cOut[n] = red[0] / (float)CONVN;
}

// ---------------------------------------------------------------------------
// 2) Scalar attention (EMBED_DIM = 1); max(qi*k_j) is at a k extremum
// ---------------------------------------------------------------------------
__global__ void attn_kernel(const float* __restrict__ c,
                            const float* __restrict__ rot,
                            const float* __restrict__ ent,
                            float* __restrict__ a) {
    __shared__ float cs[BB];
    __shared__ float kk[BB];
    __shared__ float rmn[16], rmx[16];
    const int t = threadIdx.x;
    const float e = ent[0];
    float cv = c[t];
    cs[t] = cv;
    float kv = cv * e;
    kk[t] = kv;
    // block reduce min/max of kk
    float mn = kv, mx = kv;
    #pragma unroll
    for (int off = 16; off > 0; off >>= 1) {
        mn = fminf(mn, __shfl_down_sync(0xFFFFFFFFu, mn, off));
        mx = fmaxf(mx, __shfl_down_sync(0xFFFFFFFFu, mx, off));
    }
    if ((t & 31) == 0) { rmn[t >> 5] = mn; rmx[t >> 5] = mx; }
    __syncthreads();
    float kmn = rmn[0], kmx = rmx[0];
    #pragma unroll
    for (int w = 1; w < 16; w++) { kmn = fminf(kmn, rmn[w]); kmx = fmaxf(kmx, rmx[w]); }
    const float qi = cv * rot[0];
    const float m = fmaxf(qi * kmn, qi * kmx);
    float se = 0.0f, sa = 0.0f;
    for (int j = 0; j < BB; j++) {
        float ex = __expf(qi * kk[j] - m);
        se += ex;
        sa += ex * cs[j];
    }
    a[t] = sa / se;
}

// ---------------------------------------------------------------------------
// 3) Layer 1 (rank-1): act = tanh(a_i * W1[j] + b1[j]); fp32 + fp16 hi/lo
// ---------------------------------------------------------------------------
__global__ void layer1_kernel(const float* __restrict__ a,
                              const float* __restrict__ W1,
                              const float* __restrict__ b1,
                              float* __restrict__ out,
                              __half* __restrict__ ohi,
                              __half* __restrict__ olo) {
    int idx = blockIdx.x * 256 + threadIdx.x;
    int i = idx >> 12;
    int j = idx & (DIM - 1);
    float o = tanhf(fmaf(a[i], W1[j], b1[j]));
    out[idx] = o;
    __half h = __float2half(o);
    ohi[idx] = h;
    olo[idx] = __float2half(o - __half2float(h));
}

// ---------------------------------------------------------------------------
// W -> fp16 conversion (single matrix)
// ---------------------------------------------------------------------------
__global__ void convert_w_kernel(const float* __restrict__ W,
                                 __half* __restrict__ hi) {
    int i = (blockIdx.x * 256 + threadIdx.x) * 4;
    float4 v = *(const float4*)(W + i);
    *(__half2*)(hi + i)     = __floats2half2_rn(v.x, v.y);
    *(__half2*)(hi + i + 2) = __floats2half2_rn(v.z, v.w);
}

// ---------------------------------------------------------------------------
// 4) HMMA GEMM + bias + tanh:
//    C[512,4096] = tanh(A @ W^T + b); A fp16 hi/lo, W fp16; 2-product fp32.
//    CTA tile 128x128, 8 warps (2x4), warp tile 64x32, KT=64, 4-stage cp.async.
// ---------------------------------------------------------------------------
#define KT      64
#define NT      (KDIM / KT)           // 64
#define SROW    72                    // padded row stride in halves (144 B)
#define MAT_B   (128 * SROW * 2)      // 18432 B
#define NMAT    3                     // Ahi, Alo, Wh
#define STAGE_B (NMAT * MAT_B)        // 55296 B
#define NSTAGE  4
#define BIAS_OFF (NSTAGE * STAGE_B)   // 221184
#define SMEM_REQ (BIAS_OFF + 512)

__global__ void __launch_bounds__(256, 1)
gemm_mma_kernel(const __half* __restrict__ Ahi, const __half* __restrict__ Alo,
                const __half* __restrict__ Wh,
                const float* __restrict__ bias,
                float* __restrict__ C,
                __half* __restrict__ Chi, __half* __restrict__ Clo) {
    extern __shared__ __align__(16) char smem[];
    const uint32_t sbase = smem_to_u32(smem);
    float* biasS = (float*)(smem + BIAS_OFF);

    const int t = threadIdx.x;
    const int lane = t & 31;
    const int warp = t >> 5;
    const int mw = warp >> 2;           // 0..1
    const int nw = warp & 3;            // 0..3
    const int M0 = mw * 64;
    const int N0 = nw * 32;
    const int m0 = blockIdx.y * 128;
    const int n0 = blockIdx.x * 128;

    if (t < 128) biasS[t] = bias[n0 + t];

    // producer: 3 matrices x 128 rows x 8 x 16B chunks = 3072 chunks, 12/thread
    const __half* gbase[NMAT];
    gbase[0] = Ahi + (size_t)m0 * KDIM;
    gbase[1] = Alo + (size_t)m0 * KDIM;
    gbase[2] = Wh  + (size_t)n0 * KDIM;

    #define ISSUE_STAGE(ktv) do {                                              \
        const int _kt = (ktv);                                                 \
        const uint32_t _stg = sbase + (uint32_t)(_kt & (NSTAGE - 1)) * STAGE_B;\
        _Pragma("unroll")                                                      \
        for (int _i = 0; _i < 12; _i++) {                                      \
            const int _c = _i * 256 + t;                                       \
            const int _mat = _i >> 2;                                          \
            const int _w = _c & 1023;                                          \
            const int _r = _w >> 3;                                            \
            const int _c16 = _w & 7;                                           \
            cpasync16(_stg + (uint32_t)_mat * MAT_B                            \
                           + (uint32_t)(_r * SROW + _c16 * 8) * 2,             \
                      gbase[_mat] + (size_t)_r * KDIM + _kt * KT + _c16 * 8);  \
        }                                                                      \
    } while (0)

    #pragma unroll
    for (int s = 0; s < NSTAGE - 1; s++) { ISSUE_STAGE(s); CP_COMMIT(); }

    // ldmatrix lane addressing
    const int g = lane >> 3, rin = lane & 7;
    const int rowA = M0 + (g & 1) * 8 + rin;
    const int colA = (g >> 1) * 8;
    const int rowB = N0 + (g >> 1) * 8 + rin;
    const int colB = (g & 1) * 8;

    float acc[4][4][4];
    #pragma unroll
    for (int i = 0; i < 4; i++)
        #pragma unroll
        for (int j = 0; j < 4; j++)
            #pragma unroll
            for (int k = 0; k < 4; k++) acc[i][j][k] = 0.0f;

    for (int kt = 0; kt < NT; kt++) {
        cp_wait<NSTAGE - 2>();
        __syncthreads();
        if (kt + NSTAGE - 1 < NT) ISSUE_STAGE(kt + NSTAGE - 1);
        CP_COMMIT();

        const uint32_t stg = sbase + (uint32_t)(kt & (NSTAGE - 1)) * STAGE_B;
        const uint32_t bAh = stg;
        const uint32_t bAl = stg + MAT_B;
        const uint32_t bWh = stg + 2 * MAT_B;

        #pragma unroll
        for (int h = 0; h < 4; h++) {
            const int kc = h * 16;
            uint32_t ah[4][4], al[4][4];
            #pragma unroll
            for (int mi = 0; mi < 4; mi++) {
                const uint32_t off = (uint32_t)((rowA + mi * 16) * SROW + kc + colA) * 2;
                ldsm_x4(ah[mi], bAh + off);
                ldsm_x4(al[mi], bAl + off);
            }
            uint32_t bh[2][4];
            #pragma unroll
            for (int j = 0; j < 2; j++) {
                const uint32_t off = (uint32_t)((rowB + j * 16) * SROW + kc + colB) * 2;
                ldsm_x4(bh[j], bWh + off);
            }
            #pragma unroll
            for (int mi = 0; mi < 4; mi++) {
                #pragma unroll
                for (int nj = 0; nj < 4; nj++) {
                    const int jj = nj >> 1, pp = (nj & 1) * 2;
                    mma16816h(acc[mi][nj], ah[mi], bh[jj][pp], bh[jj][pp + 1]);
                    mma16816h(acc[mi][nj], al[mi], bh[jj][pp], bh[jj][pp + 1]);
                }
            }
        }
    }

    // epilogue: bias + tanh -> fp32 C and fp16 hi/lo
    const int r0l = lane >> 2;
    const int c0l = 2 * (lane & 3);
    #pragma unroll
    for (int mi = 0; mi < 4; mi++) {
        #pragma unroll
        for (int nj = 0; nj < 4; nj++) {
            const int gnl = N0 + nj * 8 + c0l;
            const float b0 = biasS[gnl], b1 = biasS[gnl + 1];
            const int gm0 = m0 + M0 + mi * 16 + r0l;
            float v00 = tanhf(acc[mi][nj][0] + b0);
            float v01 = tanhf(acc[mi][nj][1] + b1);
            float v10 = tanhf(acc[mi][nj][2] + b0);
            float v11 = tanhf(acc[mi][nj][3] + b1);
            float* p0 = C + (size_t)gm0 * DIM + n0 + gnl;
            float* p1 = p0 + (size_t)8 * DIM;
            *(float2*)p0 = make_float2(v00, v01);
            *(float2*)p1 = make_float2(v10, v11);
            if (Chi != nullptr) {
                __half h00 = __float2half(v00);
                __half h01 = __float2half(v01);
                __half h10 = __float2half(v10);
                __half h11 = __float2half(v11);
                __half2 hp0; hp0.x = h00; hp0.y = h01;
                __half2 hp1; hp1.x = h10; hp1.y = h11;
                *(__half2*)(Chi + (size_t)gm0 * DIM + n0 + gnl) = hp0;
                *(__half2*)(Chi + (size_t)(gm0 + 8) * DIM + n0 + gnl) = hp1;
                __half2 lp0, lp1;
                lp0.x = __float2half(v00 - __half2float(h00));
                lp0.y = __float2half(v01 - __half2float(h01));
                lp1.x = __float2half(v10 - __half2float(h10));
                lp1.y = __float2half(v11 - __half2float(h11));
                *(__half2*)(Clo + (size_t)gm0 * DIM + n0 + gnl) = lp0;
                *(__half2*)(Clo + (size_t)(gm0 + 8) * DIM + n0 + gnl) = lp1;
            }
        }
    }
}

// ---------------------------------------------------------------------------
// 5) Fidelity dots (deterministic 2-stage reduction)
// ---------------------------------------------------------------------------
__global__ void fid_kernel(const float* __restrict__ a1, const float* __restrict__ a2,
                           const float* __restrict__ a3, const float* __restrict__ a4) {
    double s[10];
    #pragma unroll
    for (int k = 0; k < 10; k++) s[k] = 0.0;
    const int stride = gridDim.x * blockDim.x;
    for (int idx = blockIdx.x * blockDim.x + threadIdx.x; idx < OUTN; idx += stride) {
        double v1 = (double)a1[idx], v2 = (double)a2[idx];
        double v3 = (double)a3[idx], v4 = (double)a4[idx];
        s[0] += v1 * v1; s[1] += v1 * v2; s[2] += v1 * v3; s[3] += v1 * v4;
        s[4] += v2 * v2; s[5] += v2 * v3; s[6] += v2 * v4;
        s[7] += v3 * v3; s[8] += v3 * v4;
        s[9] += v4 * v4;
    }
    #pragma unroll
    for (int k = 0; k < 10; k++)
        #pragma unroll
        for (int off = 16; off > 0; off >>= 1)
            s[k] += __shfl_down_sync(0xFFFFFFFFu, s[k], off);
    __shared__ double ws[8][10];
    const int wid = threadIdx.x >> 5, lid = threadIdx.x & 31;
    if (lid == 0)
        #pragma unroll
        for (int k = 0; k < 10; k++) ws[wid][k] = s[k];
    __syncthreads();
    if (threadIdx.x == 0) {
        #pragma unroll
        for (int k = 0; k < 10; k++) {
            double acc = 0.0;
            for (int w = 0; w < 8; w++) acc += ws[w][k];
            g_partials[blockIdx.x * 10 + k] = acc;
        }
    }
}

__global__ void finalize_kernel(float* __restrict__ wout) {
    __shared__ double dots[10];
    const int t = threadIdx.x;
    const int w = t >> 5, lid = t & 31;
    if (w < 10) {
        double acc = 0.0;
        for (int p = lid; p < FID_BLOCKS; p += 32) acc += g_partials[p * 10 + w];
        #pragma unroll
        for (int off = 16; off > 0; off >>= 1)
            acc += __shfl_down_sync(0xFFFFFFFFu, acc, off);
        if (lid == 0) dots[w] = acc;
    }
    __syncthreads();
    if (t < 16) {
        int i = t >> 2, j = t & 3;
        int ii = i < j ? i : j, jj = i < j ? j : i;
        const int base[4] = {0, 4, 7, 9};
        double dij = dots[base[ii] + (jj - ii)];
        double dii = dots[base[ii]];
        double djj = dots[base[jj]];
        double ni = sqrt(dii) + 1e-12;
        double nj = sqrt(djj) + 1e-12;
        double sh = dij / (ni * nj);
        double fid = sh * sh;
        wout[t] = (fid >= 0.8 && i != j) ? 1.0f : 0.0f;
    }
}

// ---------------------------------------------------------------------------
// kernel_launch  (ordered so launch index 5 == first GEMM, for ncu -s 5)
// ---------------------------------------------------------------------------
extern "C" void kernel_launch(void* const* d_in, const int* in_sizes, int n_in,
                              void* d_out, int out_size) {
    const float* x   = (const float*)d_in[0];
    const float* cw  = (const float*)d_in[1];
    const float* cb  = (const float*)d_in[2];
    const float* rot = (const float*)d_in[3];
    const float* ent = (const float*)d_in[4];
    const float* W1  = (const float*)d_in[5];
    const float* b1  = (const float*)d_in[6];
    const float* W2  = (const float*)d_in[7];
    const float* b2  = (const float*)d_in[8];
    const float* W3  = (const float*)d_in[9];
    const float* b3  = (const float*)d_in[10];
    const float* W4  = (const float*)d_in[11];
    const float* b4  = (const float*)d_in[12];
    float* out = (float*)d_out;

    float *gc, *ga, *ga1, *ga2, *ga3;
    __half *ahi, *alo, *wh;
    cudaGetSymbolAddress((void**)&gc,  g_c);
    cudaGetSymbolAddress((void**)&ga,  g_a);
    cudaGetSymbolAddress((void**)&ga1, g_act1);
    cudaGetSymbolAddress((void**)&ga2, g_act2);
    cudaGetSymbolAddress((void**)&ga3, g_act3);
    cudaGetSymbolAddress((void**)&ahi, g_ahi);
    cudaGetSymbolAddress((void**)&alo, g_alo);
    cudaGetSymbolAddress((void**)&wh,  g_wh);

    cudaFuncSetAttribute(gemm_mma_kernel,
                         cudaFuncAttributeMaxDynamicSharedMemorySize, SMEM_REQ);

    const size_t WN = (size_t)DIM * KDIM;
    dim3 ggrid(DIM / 128, BB / 128);  // (32, 4)

    conv_kernel<<<BB, 256>>>(x, cw, cb, gc);                       // 0
    attn_kernel<<<1, BB>>>(gc, rot, ent, ga);                      // 1
    convert_w_kernel<<<(int)(WN / 1024), 256>>>(W2, wh + 0 * WN);  // 2
    layer1_kernel<<<OUTN / 256, 256>>>(ga, W1, b1, ga1,            // 3
                                       ahi + 0 * (size_t)OUTN, alo + 0 * (size_t)OUTN);
    convert_w_kernel<<<(int)(WN / 1024), 256>>>(W3, wh + 1 * WN);  // 4
    gemm_mma_kernel<<<ggrid, 256, SMEM_REQ>>>(                     // 5  <- ncu -s 5
        ahi + 0 * (size_t)OUTN, alo + 0 * (size_t)OUTN,
        wh + 0 * WN, b2, ga2,
        ahi + 1 * (size_t)OUTN, alo + 1 * (size_t)OUTN);
    convert_w_kernel<<<(int)(WN / 1024), 256>>>(W4, wh + 2 * WN);  // 6
    gemm_mma_kernel<<<ggrid, 256, SMEM_REQ>>>(                     // 7
        ahi + 1 * (size_t)OUTN, alo + 1 * (size_t)OUTN,
        wh + 1 * WN, b3, ga3,
        ahi + 2 * (size_t)OUTN, alo + 2 * (size_t)OUTN);
    gemm_mma_kernel<<<ggrid, 256, SMEM_REQ>>>(                     // 8
        ahi + 2 * (size_t)OUTN, alo + 2 * (size_t)OUTN,
        wh + 2 * WN, b4, out,
        nullptr, nullptr);

    fid_kernel<<<FID_BLOCKS, 256>>>(ga1, ga2, ga3, out);           // 9
    finalize_kernel<<<1, 320>>>(out + OUTN);                       // 10
}

// round 5
// speedup vs baseline: 2.6715x; 1.5214x over previous
#include <cuda_runtime.h>
#include <cuda_bf16.h>
#include <cuda_fp16.h>
#include <math.h>
#include <stdint.h>

// ---------------------------------------------------------------------------
// Problem constants
// ---------------------------------------------------------------------------
#define BB   512
#define HH   128
#define WW   128
#define CONVN 16129
#define DIM  4096
#define KDIM 4096
#define OUTN (BB * DIM)

// ---------------------------------------------------------------------------
// Scratch (__device__ globals; no cudaMalloc allowed)
// ---------------------------------------------------------------------------
__device__ float g_c[BB];
__device__ float g_a[BB];
__device__ float g_act1[OUTN];
__device__ float g_act2[OUTN];
__device__ float g_act3[OUTN];
__device__ __half g_ahi[3][OUTN];
__device__ __half g_alo[3][OUTN];
__device__ __half g_wh[3][DIM * KDIM];
#define FID_BLOCKS 512
__device__ double g_partials[FID_BLOCKS * 10];

// ---------------------------------------------------------------------------
// PTX helpers (plain-PTX, valid on non-'a' targets)
// ---------------------------------------------------------------------------
__device__ __forceinline__ uint32_t smem_to_u32(const void* p) {
    uint32_t a;
    asm("{ .reg .u64 t; cvta.to.shared.u64 t, %1; cvt.u32.u64 %0, t; }"
        : "=r"(a) : "l"(p));
    return a;
}
__device__ __forceinline__ void cpasync16(uint32_t dst, const void* gsrc) {
    asm volatile("cp.async.cg.shared.global [%0], [%1], 16;"
                 :: "r"(dst), "l"(__cvta_generic_to_global(gsrc)) : "memory");
}
#define CP_COMMIT() asm volatile("cp.async.commit_group;" ::: "memory")
template <int N>
__device__ __forceinline__ void cp_wait() {
    asm volatile("cp.async.wait_group %0;" :: "n"(N) : "memory");
}
__device__ __forceinline__ void ldsm_x4(uint32_t r[4], uint32_t addr) {
    asm volatile("ldmatrix.sync.aligned.m8n8.x4.shared.b16 {%0,%1,%2,%3}, [%4];"
                 : "=r"(r[0]), "=r"(r[1]), "=r"(r[2]), "=r"(r[3]) : "r"(addr));
}
__device__ __forceinline__ void mma16816h(float d[4], const uint32_t a[4],
                                          uint32_t b0, uint32_t b1) {
    asm volatile(
        "mma.sync.aligned.m16n8k16.row.col.f32.f16.f16.f32 "
        "{%0,%1,%2,%3}, {%4,%5,%6,%7}, {%8,%9}, {%0,%1,%2,%3};"
        : "+f"(d[0]), "+f"(d[1]), "+f"(d[2]), "+f"(d[3])
        : "r"(a[0]), "r"(a[1]), "r"(a[2]), "r"(a[3]), "r"(b0), "r"(b1));
}

// ---------------------------------------------------------------------------
// 1) Conv 2x2 valid + bias + sigmoid + mean -> g_c[n]
// ---------------------------------------------------------------------------
__global__ void conv_kernel(const float* __restrict__ x,
                            const float* __restrict__ cw,
                            const float* __restrict__ cb,
                            float* __restrict__ cOut) {
    const int n = blockIdx.x;
    const float* xp = x + n * HH * WW;
    const float w00 = cw[0], w01 = cw[1], w10 = cw[2], w11 = cw[3];
    const float bias = cb[0];
    float s = 0.0f;
    for (int idx = threadIdx.x; idx < 127 * 32; idx += 256) {
        const int i = idx >> 5;
        const int j = (idx & 31) * 4;
        const float* r0 = xp + i * WW + j;
        const float* r1 = r0 + WW;
        float4 a = *(const float4*)r0;
        float4 b = *(const float4*)r1;
        float a4 = 0.0f, b4 = 0.0f;
        if (j + 4 < WW) { a4 = r0[4]; b4 = r1[4]; }
        float x0[5] = {a.x, a.y, a.z, a.w, a4};
        float x1[5] = {b.x, b.y, b.z, b.w, b4};
        #pragma unroll
        for (int k = 0; k < 4; k++) {
            if (j + k < 127) {
                float v = x0[k] * w00 + x0[k + 1] * w01
                        + x1[k] * w10 + x1[k + 1] * w11 + bias;
                s += 1.0f / (1.0f + __expf(-v));
            }
        }
    }
    __shared__ float red[256];
    red[threadIdx.x] = s;
    __syncthreads();
    #pragma unroll
    for (int off = 128; off > 0; off >>= 1) {
        if (threadIdx.x < off) red[threadIdx.x] += red[threadIdx.x + off];
        __syncthreads();
    }
    if (threadIdx.x == 0) cOut[n] = red[0] / (float)CONVN;
}

// ---------------------------------------------------------------------------
// 2) Scalar attention (EMBED_DIM = 1)
// ---------------------------------------------------------------------------
__global__ void attn_kernel(const float* __restrict__ c,
                            const float* __restrict__ rot,
                            const float* __restrict__ ent,
                            float* __restrict__ a) {
    __shared__ float cs[BB];
    __shared__ float kk[BB];
    __shared__ float rmn[16], rmx[16];
    const int t = threadIdx.x;
    const float e = ent[0];
    float cv = c[t];
    cs[t] = cv;
    float kv = cv * e;
    kk[t] = kv;
    float mn = kv, mx = kv;
    #pragma unroll
    for (int off = 16; off > 0; off >>= 1) {
        mn = fminf(mn, __shfl_down_sync(0xFFFFFFFFu, mn, off));
        mx = fmaxf(mx, __shfl_down_sync(0xFFFFFFFFu, mx, off));
    }
    if ((t & 31) == 0) { rmn[t >> 5] = mn; rmx[t >> 5] = mx; }
    __syncthreads();
    float kmn = rmn[0], kmx = rmx[0];
    #pragma unroll
    for (int w = 1; w < 16; w++) { kmn = fminf(kmn, rmn[w]); kmx = fmaxf(kmx, rmx[w]); }
    const float qi = cv * rot[0];
    const float m = fmaxf(qi * kmn, qi * kmx);
    float se = 0.0f, sa = 0.0f;
    for (int j = 0; j < BB; j++) {
        float ex = __expf(qi * kk[j] - m);
        se += ex;
        sa += ex * cs[j];
    }
    a[t] = sa / se;
}

// ---------------------------------------------------------------------------
// 3) Layer 1 (rank-1): act = tanh(a_i * W1[j] + b1[j]); fp32 + fp16 hi/lo
// ---------------------------------------------------------------------------
__global__ void layer1_kernel(const float* __restrict__ a,
                              const float* __restrict__ W1,
                              const float* __restrict__ b1,
                              float* __restrict__ out,
                              __half* __restrict__ ohi,
                              __half* __restrict__ olo) {
    int idx = blockIdx.x * 256 + threadIdx.x;
    int i = idx >> 12;
    int j = idx & (DIM - 1);
    float o = tanhf(fmaf(a[i], W1[j], b1[j]));
    out[idx] = o;
    __half h = __float2half(o);
    ohi[idx] = h;
    olo[idx] = __float2half(o - __half2float(h));
}

// ---------------------------------------------------------------------------
// W -> fp16 conversion
// ---------------------------------------------------------------------------
__global__ void convert_w_kernel(const float* __restrict__ W,
                                 __half* __restrict__ hi) {
    int i = (blockIdx.x * 256 + threadIdx.x) * 4;
    float4 v = *(const float4*)(W + i);
    *(__half2*)(hi + i)     = __floats2half2_rn(v.x, v.y);
    *(__half2*)(hi + i + 2) = __floats2half2_rn(v.z, v.w);
}

// ---------------------------------------------------------------------------
// 4) HMMA GEMM + bias + tanh:
//    C[512,4096] = tanh(A @ W^T + b); A fp16 hi/lo, W fp16; 2-product fp32.
//    CTA tile 128x128, 16 warps (4x4), warp tile 32x32, KT=64, 3-stage cp.async.
// ---------------------------------------------------------------------------
#define KT      64
#define NT      (KDIM / KT)           // 64
#define SROW    72                    // padded row stride in halves (144 B)
#define MAT_B   (128 * SROW * 2)      // 18432 B
#define NMAT    3                     // Ahi, Alo, Wh
#define STAGE_B (NMAT * MAT_B)        // 55296 B
#define NSTAGE  3
#define BIAS_OFF (NSTAGE * STAGE_B)   // 165888
#define SMEM_REQ (BIAS_OFF + 512)

__global__ void __launch_bounds__(512, 1)
gemm_mma_kernel(const __half* __restrict__ Ahi, const __half* __restrict__ Alo,
                const __half* __restrict__ Wh,
                const float* __restrict__ bias,
                float* __restrict__ C,
                __half* __restrict__ Chi, __half* __restrict__ Clo) {
    extern __shared__ __align__(16) char smem[];
    const uint32_t sbase = smem_to_u32(smem);
    float* biasS = (float*)(smem + BIAS_OFF);

    const int t = threadIdx.x;
    const int lane = t & 31;
    const int warp = t >> 5;            // 0..15
    const int mw = warp >> 2;           // 0..3
    const int nw = warp & 3;            // 0..3
    const int M0 = mw * 32;
    const int N0 = nw * 32;
    const int m0 = blockIdx.y * 128;
    const int n0 = blockIdx.x * 128;

    if (t < 128) biasS[t] = bias[n0 + t];

    // producer: 3 mats x 128 rows x 8 x 16B chunks = 3072 chunks, 6/thread
    const __half* gbase[NMAT];
    gbase[0] = Ahi + (size_t)m0 * KDIM;
    gbase[1] = Alo + (size_t)m0 * KDIM;
    gbase[2] = Wh  + (size_t)n0 * KDIM;

    #define ISSUE_STAGE(ktv, slot) do {                                        \
        const int _kt = (ktv);                                                 \
        const uint32_t _stg = sbase + (uint32_t)(slot) * STAGE_B;              \
        _Pragma("unroll")                                                      \
        for (int _i = 0; _i < 6; _i++) {                                       \
            const int _c = _i * 512 + t;                                       \
            const int _mat = _c >> 10;                                         \
            const int _w = _c & 1023;                                          \
            const int _r = _w >> 3;                                            \
            const int _c16 = _w & 7;                                           \
            cpasync16(_stg + (uint32_t)_mat * MAT_B                            \
                           + (uint32_t)(_r * SROW + _c16 * 8) * 2,             \
                      gbase[_mat] + (size_t)_r * KDIM + _kt * KT + _c16 * 8);  \
        }                                                                      \
    } while (0)

    ISSUE_STAGE(0, 0); CP_COMMIT();
    ISSUE_STAGE(1, 1); CP_COMMIT();

    // ldmatrix lane addressing
    const int g = lane >> 3, rin = lane & 7;
    const int rowA = M0 + (g & 1) * 8 + rin;   // + mi*16
    const int colA = (g >> 1) * 8;
    const int rowB = N0 + (g >> 1) * 8 + rin;  // + j*16
    const int colB = (g & 1) * 8;

    float acc[2][4][4];
    #pragma unroll
    for (int i = 0; i < 2; i++)
        #pragma unroll
        for (int j = 0; j < 4; j++)
            #pragma unroll
            for (int k = 0; k < 4; k++) acc[i][j][k] = 0.0f;

    int slot = 0, wslot = 2;
    for (int kt = 0; kt < NT; kt++) {
        cp_wait<NSTAGE - 2>();
        __syncthreads();
        if (kt + 2 < NT) ISSUE_STAGE(kt + 2, wslot);
        CP_COMMIT();
        if (++wslot == NSTAGE) wslot = 0;

        const uint32_t stg = sbase + (uint32_t)slot * STAGE_B;
        if (++slot == NSTAGE) slot = 0;
        const uint32_t bAh = stg;
        const uint32_t bAl = stg + MAT_B;
        const uint32_t bWh = stg + 2 * MAT_B;

        #pragma unroll
        for (int h = 0; h < 4; h++) {
            const int kc = h * 16;
            uint32_t ah[2][4], al[2][4];
            #pragma unroll
            for (int mi = 0; mi < 2; mi++) {
                const uint32_t off = (uint32_t)((rowA + mi * 16) * SROW + kc + colA) * 2;
                ldsm_x4(ah[mi], bAh + off);
                ldsm_x4(al[mi], bAl + off);
            }
            uint32_t bh[2][4];
            #pragma unroll
            for (int j = 0; j < 2; j++) {
                const uint32_t off = (uint32_t)((rowB + j * 16) * SROW + kc + colB) * 2;
                ldsm_x4(bh[j], bWh + off);
            }
            // all hi-product MMAs first (8 independent), then lo-product
            #pragma unroll
            for (int mi = 0; mi < 2; mi++)
                #pragma unroll
                for (int nj = 0; nj < 4; nj++) {
                    const int jj = nj >> 1, pp = (nj & 1) * 2;
                    mma16816h(acc[mi][nj], ah[mi], bh[jj][pp], bh[jj][pp + 1]);
                }
            #pragma unroll
            for (int mi = 0; mi < 2; mi++)
                #pragma unroll
                for (int nj = 0; nj < 4; nj++) {
                    const int jj = nj >> 1, pp = (nj & 1) * 2;
                    mma16816h(acc[mi][nj], al[mi], bh[jj][pp], bh[jj][pp + 1]);
                }
        }
    }

    // epilogue: bias + tanh -> fp32 C and fp16 hi/lo
    const int r0l = lane >> 2;
    const int c0l = 2 * (lane & 3);
    #pragma unroll
    for (int mi = 0; mi < 2; mi++) {
        #pragma unroll
        for (int nj = 0; nj < 4; nj++) {
            const int gnl = N0 + nj * 8 + c0l;
            const float b0 = biasS[gnl], b1 = biasS[gnl + 1];
            const int gm0 = m0 + M0 + mi * 16 + r0l;
            float v00 = tanhf(acc[mi][nj][0] + b0);
            float v01 = tanhf(acc[mi][nj][1] + b1);
            float v10 = tanhf(acc[mi][nj][2] + b0);
            float v11 = tanhf(acc[mi][nj][3] + b1);
            float* p0 = C + (size_t)gm0 * DIM + n0 + gnl;
            float* p1 = p0 + (size_t)8 * DIM;
            *(float2*)p0 = make_float2(v00, v01);
            *(float2*)p1 = make_float2(v10, v11);
            if (Chi != nullptr) {
                __half h00 = __float2half(v00);
                __half h01 = __float2half(v01);
                __half h10 = __float2half(v10);
                __half h11 = __float2half(v11);
                __half2 hp0; hp0.x = h00; hp0.y = h01;
                __half2 hp1; hp1.x = h10; hp1.y = h11;
                *(__half2*)(Chi + (size_t)gm0 * DIM + n0 + gnl) = hp0;
                *(__half2*)(Chi + (size_t)(gm0 + 8) * DIM + n0 + gnl) = hp1;
                __half2 lp0, lp1;
                lp0.x = __float2half(v00 - __half2float(h00));
                lp0.y = __float2half(v01 - __half2float(h01));
                lp1.x = __float2half(v10 - __half2float(h10));
                lp1.y = __float2half(v11 - __half2float(h11));
                *(__half2*)(Clo + (size_t)gm0 * DIM + n0 + gnl) = lp0;
                *(__half2*)(Clo + (size_t)(gm0 + 8) * DIM + n0 + gnl) = lp1;
            }
        }
    }
}

// ---------------------------------------------------------------------------
// 5) Fidelity dots (deterministic 2-stage reduction)
// ---------------------------------------------------------------------------
__global__ void fid_kernel(const float* __restrict__ a1, const float* __restrict__ a2,
                           const float* __restrict__ a3, const float* __restrict__ a4) {
    double s[10];
    #pragma unroll
    for (int k = 0; k < 10; k++) s[k] = 0.0;
    const int stride = gridDim.x * blockDim.x;
    for (int idx = blockIdx.x * blockDim.x + threadIdx.x; idx < OUTN; idx += stride) {
        double v1 = (double)a1[idx], v2 = (double)a2[idx];
        double v3 = (double)a3[idx], v4 = (double)a4[idx];
        s[0] += v1 * v1; s[1] += v1 * v2; s[2] += v1 * v3; s[3] += v1 * v4;
        s[4] += v2 * v2; s[5] += v2 * v3; s[6] += v2 * v4;
        s[7] += v3 * v3; s[8] += v3 * v4;
        s[9] += v4 * v4;
    }
    #pragma unroll
    for (int k = 0; k < 10; k++)
        #pragma unroll
        for (int off = 16; off > 0; off >>= 1)
            s[k] += __shfl_down_sync(0xFFFFFFFFu, s[k], off);
    __shared__ double ws[8][10];
    const int wid = threadIdx.x >> 5, lid = threadIdx.x & 31;
    if (lid == 0)
        #pragma unroll
        for (int k = 0; k < 10; k++) ws[wid][k] = s[k];
    __syncthreads();
    if (threadIdx.x == 0) {
        #pragma unroll
        for (int k = 0; k < 10; k++) {
            double acc = 0.0;
            for (int w = 0; w < 8; w++) acc += ws[w][k];
            g_partials[blockIdx.x * 10 + k] = acc;
        }
    }
}

__global__ void finalize_kernel(float* __restrict__ wout) {
    __shared__ double dots[10];
    const int t = threadIdx.x;
    const int w = t >> 5, lid = t & 31;
    if (w < 10) {
        double acc = 0.0;
        for (int p = lid; p < FID_BLOCKS; p += 32) acc += g_partials[p * 10 + w];
        #pragma unroll
        for (int off = 16; off > 0; off >>= 1)
            acc += __shfl_down_sync(0xFFFFFFFFu, acc, off);
        if (lid == 0) dots[w] = acc;
    }
    __syncthreads();
    if (t < 16) {
        int i = t >> 2, j = t & 3;
        int ii = i < j ? i : j, jj = i < j ? j : i;
        const int base[4] = {0, 4, 7, 9};
        double dij = dots[base[ii] + (jj - ii)];
        double dii = dots[base[ii]];
        double djj = dots[base[jj]];
        double ni = sqrt(dii) + 1e-12;
        double nj = sqrt(djj) + 1e-12;
        double sh = dij / (ni * nj);
        double fid = sh * sh;
        wout[t] = (fid >= 0.8 && i != j) ? 1.0f : 0.0f;
    }
}

// ---------------------------------------------------------------------------
// kernel_launch
// ---------------------------------------------------------------------------
extern "C" void kernel_launch(void* const* d_in, const int* in_sizes, int n_in,
                              void* d_out, int out_size) {
    const float* x   = (const float*)d_in[0];
    const float* cw  = (const float*)d_in[1];
    const float* cb  = (const float*)d_in[2];
    const float* rot = (const float*)d_in[3];
    const float* ent = (const float*)d_in[4];
    const float* W1  = (const float*)d_in[5];
    const float* b1  = (const float*)d_in[6];
    const float* W2  = (const float*)d_in[7];
    const float* b2  = (const float*)d_in[8];
    const float* W3  = (const float*)d_in[9];
    const float* b3  = (const float*)d_in[10];
    const float* W4  = (const float*)d_in[11];
    const float* b4  = (const float*)d_in[12];
    float* out = (float*)d_out;

    float *gc, *ga, *ga1, *ga2, *ga3;
    __half *ahi, *alo, *wh;
    cudaGetSymbolAddress((void**)&gc,  g_c);
    cudaGetSymbolAddress((void**)&ga,  g_a);
    cudaGetSymbolAddress((void**)&ga1, g_act1);
    cudaGetSymbolAddress((void**)&ga2, g_act2);
    cudaGetSymbolAddress((void**)&ga3, g_act3);
    cudaGetSymbolAddress((void**)&ahi, g_ahi);
    cudaGetSymbolAddress((void**)&alo, g_alo);
    cudaGetSymbolAddress((void**)&wh,  g_wh);

    cudaFuncSetAttribute(gemm_mma_kernel,
                         cudaFuncAttributeMaxDynamicSharedMemorySize, SMEM_REQ);

    const size_t WN = (size_t)DIM * KDIM;
    dim3 ggrid(DIM / 128, BB / 128);  // (32, 4)

    conv_kernel<<<BB, 256>>>(x, cw, cb, gc);                       // 0
    attn_kernel<<<1, BB>>>(gc, rot, ent, ga);                      // 1
    convert_w_kernel<<<(int)(WN / 1024), 256>>>(W2, wh + 0 * WN);  // 2
    layer1_kernel<<<OUTN / 256, 256>>>(ga, W1, b1, ga1,            // 3
                                       ahi + 0 * (size_t)OUTN, alo + 0 * (size_t)OUTN);
    convert_w_kernel<<<(int)(WN / 1024), 256>>>(W3, wh + 1 * WN);  // 4
    gemm_mma_kernel<<<ggrid, 512, SMEM_REQ>>>(                     // 5
        ahi + 0 * (size_t)OUTN, alo + 0 * (size_t)OUTN,
        wh + 0 * WN, b2, ga2,
        ahi + 1 * (size_t)OUTN, alo + 1 * (size_t)OUTN);
    convert_w_kernel<<<(int)(WN / 1024), 256>>>(W4, wh + 2 * WN);  // 6
    gemm_mma_kernel<<<ggrid, 512, SMEM_REQ>>>(                     // 7
        ahi + 1 * (size_t)OUTN, alo + 1 * (size_t)OUTN,
        wh + 1 * WN, b3, ga3,
        ahi + 2 * (size_t)OUTN, alo + 2 * (size_t)OUTN);
    gemm_mma_kernel<<<ggrid, 512, SMEM_REQ>>>(                     // 8
        ahi + 2 * (size_t)OUTN, alo + 2 * (size_t)OUTN,
        wh + 2 * WN, b4, out,
        nullptr, nullptr);

    fid_kernel<<<FID_BLOCKS, 256>>>(ga1, ga2, ga3, out);           // 9
    finalize_kernel<<<1, 320>>>(out + OUTN);                       // 10
}

// round 6
// speedup vs baseline: 3.4349x; 1.2858x over previous
#include <cuda_runtime.h>
#include <cuda_bf16.h>
#include <cuda_fp16.h>
#include <math.h>
#include <stdint.h>

// ---------------------------------------------------------------------------
// Problem constants
// ---------------------------------------------------------------------------
#define BB   512
#define HH   128
#define WW   128
#define CONVN 16129
#define DIM  4096
#define KDIM 4096
#define OUTN (BB * DIM)

// ---------------------------------------------------------------------------
// Scratch (__device__ globals; no cudaMalloc allowed)
// ---------------------------------------------------------------------------
__device__ float g_c[BB];
__device__ float g_a[BB];
__device__ float g_act1[OUTN];
__device__ float g_act2[OUTN];
__device__ float g_act3[OUTN];
__device__ __half g_ah[3][OUTN];
__device__ __half g_wh[3][DIM * KDIM];
#define FID_BLOCKS 512
__device__ double g_partials[FID_BLOCKS * 10];

// ---------------------------------------------------------------------------
// PTX helpers (plain-PTX, valid on non-'a' targets)
// ---------------------------------------------------------------------------
__device__ __forceinline__ uint32_t smem_to_u32(const void* p) {
    uint32_t a;
    asm("{ .reg .u64 t; cvta.to.shared.u64 t, %1; cvt.u32.u64 %0, t; }"
        : "=r"(a) : "l"(p));
    return a;
}
__device__ __forceinline__ void cpasync16(uint32_t dst, const void* gsrc) {
    asm volatile("cp.async.cg.shared.global [%0], [%1], 16;"
                 :: "r"(dst), "l"(__cvta_generic_to_global(gsrc)) : "memory");
}
#define CP_COMMIT() asm volatile("cp.async.commit_group;" ::: "memory")
template <int N>
__device__ __forceinline__ void cp_wait() {
    asm volatile("cp.async.wait_group %0;" :: "n"(N) : "memory");
}
__device__ __forceinline__ void ldsm_x4(uint32_t r[4], uint32_t addr) {
    asm volatile("ldmatrix.sync.aligned.m8n8.x4.shared.b16 {%0,%1,%2,%3}, [%4];"
                 : "=r"(r[0]), "=r"(r[1]), "=r"(r[2]), "=r"(r[3]) : "r"(addr));
}
__device__ __forceinline__ void mma16816h(float d[4], const uint32_t a[4],
                                          uint32_t b0, uint32_t b1) {
    asm volatile(
        "mma.sync.aligned.m16n8k16.row.col.f32.f16.f16.f32 "
        "{%0,%1,%2,%3}, {%4,%5,%6,%7}, {%8,%9}, {%0,%1,%2,%3};"
        : "+f"(d[0]), "+f"(d[1]), "+f"(d[2]), "+f"(d[3])
        : "r"(a[0]), "r"(a[1]), "r"(a[2]), "r"(a[3]), "r"(b0), "r"(b1));
}

// ---------------------------------------------------------------------------
// 1) Conv 2x2 valid + bias + sigmoid + mean -> g_c[n]
// ---------------------------------------------------------------------------
__global__ void conv_kernel(const float* __restrict__ x,
                            const float* __restrict__ cw,
                            const float* __restrict__ cb,
                            float* __restrict__ cOut) {
    const int n = blockIdx.x;
    const float* xp = x + n * HH * WW;
    const float w00 = cw[0], w01 = cw[1], w10 = cw[2], w11 = cw[3];
    const float bias = cb[0];
    float s = 0.0f;
    for (int idx = threadIdx.x; idx < 127 * 32; idx += 256) {
        const int i = idx >> 5;
        const int j = (idx & 31) * 4;
        const float* r0 = xp + i * WW + j;
        const float* r1 = r0 + WW;
        float4 a = *(const float4*)r0;
        float4 b = *(const float4*)r1;
        float a4 = 0.0f, b4 = 0.0f;
        if (j + 4 < WW) { a4 = r0[4]; b4 = r1[4]; }
        float x0[5] = {a.x, a.y, a.z, a.w, a4};
        float x1[5] = {b.x, b.y, b.z, b.w, b4};
        #pragma unroll
        for (int k = 0; k < 4; k++) {
            if (j + k < 127) {
                float v = x0[k] * w00 + x0[k + 1] * w01
                        + x1[k] * w10 + x1[k + 1] * w11 + bias;
                s += 1.0f / (1.0f + __expf(-v));
            }
        }
    }
    __shared__ float red[256];
    red[threadIdx.x] = s;
    __syncthreads();
    #pragma unroll
    for (int off = 128; off > 0; off >>= 1) {
        if (threadIdx.x < off) red[threadIdx.x] += red[threadIdx.x + off];
        __syncthreads();
    }
    if (threadIdx.x == 0) cOut[n] = red[0] / (float)CONVN;
}

// ---------------------------------------------------------------------------
// 2) Scalar attention (EMBED_DIM = 1)
// ---------------------------------------------------------------------------
__global__ void attn_kernel(const float* __restrict__ c,
                            const float* __restrict__ rot,
                            const float* __restrict__ ent,
                            float* __restrict__ a) {
    __shared__ float cs[BB];
    __shared__ float kk[BB];
    __shared__ float rmn[16], rmx[16];
    const int t = threadIdx.x;
    const float e = ent[0];
    float cv = c[t];
    cs[t] = cv;
    float kv = cv * e;
    kk[t] = kv;
    float mn = kv, mx = kv;
    #pragma unroll
    for (int off = 16; off > 0; off >>= 1) {
        mn = fminf(mn, __shfl_down_sync(0xFFFFFFFFu, mn, off));
        mx = fmaxf(mx, __shfl_down_sync(0xFFFFFFFFu, mx, off));
    }
    if ((t & 31) == 0) { rmn[t >> 5] = mn; rmx[t >> 5] = mx; }
    __syncthreads();
    float kmn = rmn[0], kmx = rmx[0];
    #pragma unroll
    for (int w = 1; w < 16; w++) { kmn = fminf(kmn, rmn[w]); kmx = fmaxf(kmx, rmx[w]); }
    const float qi = cv * rot[0];
    const float m = fmaxf(qi * kmn, qi * kmx);
    float se = 0.0f, sa = 0.0f;
    for (int j = 0; j < BB; j++) {
        float ex = __expf(qi * kk[j] - m);
        se += ex;
        sa += ex * cs[j];
    }
    a[t] = sa / se;
}

// ---------------------------------------------------------------------------
// 3) Layer 1 (rank-1): act = tanh(a_i * W1[j] + b1[j]); fp32 + fp16
// ---------------------------------------------------------------------------
__global__ void layer1_kernel(const float* __restrict__ a,
                              const float* __restrict__ W1,
                              const float* __restrict__ b1,
                              float* __restrict__ out,
                              __half* __restrict__ oh) {
    int idx = blockIdx.x * 256 + threadIdx.x;
    int i = idx >> 12;
    int j = idx & (DIM - 1);
    float o = tanhf(fmaf(a[i], W1[j], b1[j]));
    out[idx] = o;
    oh[idx] = __float2half(o);
}

// ---------------------------------------------------------------------------
// W -> fp16 conversion
// ---------------------------------------------------------------------------
__global__ void convert_w_kernel(const float* __restrict__ W,
                                 __half* __restrict__ hi) {
    int i = (blockIdx.x * 256 + threadIdx.x) * 4;
    float4 v = *(const float4*)(W + i);
    *(__half2*)(hi + i)     = __floats2half2_rn(v.x, v.y);
    *(__half2*)(hi + i + 2) = __floats2half2_rn(v.z, v.w);
}

// ---------------------------------------------------------------------------
// 4) HMMA GEMM + bias + tanh:
//    C[512,4096] = tanh(A @ W^T + b); A, W single-rounded fp16, fp32 accum.
//    CTA tile 128x128, 16 warps (4x4), warp tile 32x32, KT=64, 4-stage cp.async.
// ---------------------------------------------------------------------------
#define KT      64
#define NT      (KDIM / KT)           // 64
#define SROW    72                    // padded row stride in halves (144 B)
#define MAT_B   (128 * SROW * 2)      // 18432 B
#define NMAT    2                     // A, W
#define STAGE_B (NMAT * MAT_B)        // 36864 B
#define NSTAGE  4
#define BIAS_OFF (NSTAGE * STAGE_B)   // 147456
#define SMEM_REQ (BIAS_OFF + 512)

__global__ void __launch_bounds__(512, 1)
gemm_mma_kernel(const __half* __restrict__ Ah,
                const __half* __restrict__ Wh,
                const float* __restrict__ bias,
                float* __restrict__ C,
                __half* __restrict__ Ch) {
    extern __shared__ __align__(16) char smem[];
    const uint32_t sbase = smem_to_u32(smem);
    float* biasS = (float*)(smem + BIAS_OFF);

    const int t = threadIdx.x;
    const int lane = t & 31;
    const int warp = t >> 5;            // 0..15
    const int mw = warp >> 2;           // 0..3
    const int nw = warp & 3;            // 0..3
    const int M0 = mw * 32;
    const int N0 = nw * 32;
    const int m0 = blockIdx.y * 128;
    const int n0 = blockIdx.x * 128;

    if (t < 128) biasS[t] = bias[n0 + t];

    // producer: 2 mats x 128 rows x 8 x 16B chunks = 2048 chunks, 4/thread
    const __half* gbase[NMAT];
    gbase[0] = Ah + (size_t)m0 * KDIM;
    gbase[1] = Wh + (size_t)n0 * KDIM;

    #define ISSUE_STAGE(ktv, slot) do {                                        \
        const int _kt = (ktv);                                                 \
        const uint32_t _stg = sbase + (uint32_t)(slot) * STAGE_B;              \
        _Pragma("unroll")                                                      \
        for (int _i = 0; _i < 4; _i++) {                                       \
            const int _c = _i * 512 + t;                                       \
            const int _mat = _c >> 10;                                         \
            const int _w = _c & 1023;                                          \
            const int _r = _w >> 3;                                            \
            const int _c16 = _w & 7;                                           \
            cpasync16(_stg + (uint32_t)_mat * MAT_B                            \
                           + (uint32_t)(_r * SROW + _c16 * 8) * 2,             \
                      gbase[_mat] + (size_t)_r * KDIM + _kt * KT + _c16 * 8);  \
        }                                                                      \
    } while (0)

    ISSUE_STAGE(0, 0); CP_COMMIT();
    ISSUE_STAGE(1, 1); CP_COMMIT();
    ISSUE_STAGE(2, 2); CP_COMMIT();

    // ldmatrix lane addressing
    const int g = lane >> 3, rin = lane & 7;
    const int rowA = M0 + (g & 1) * 8 + rin;   // + mi*16
    const int colA = (g >> 1) * 8;
    const int rowB = N0 + (g >> 1) * 8 + rin;  // + j*16
    const int colB = (g & 1) * 8;

    float acc[2][4][4];
    #pragma unroll
    for (int i = 0; i < 2; i++)
        #pragma unroll
        for (int j = 0; j < 4; j++)
            #pragma unroll
            for (int k = 0; k < 4; k++) acc[i][j][k] = 0.0f;

    for (int kt = 0; kt < NT; kt++) {
        cp_wait<NSTAGE - 2>();
        __syncthreads();
        if (kt + NSTAGE - 1 < NT) ISSUE_STAGE(kt + NSTAGE - 1, (kt + NSTAGE - 1) & 3);
        CP_COMMIT();

        const uint32_t stg = sbase + (uint32_t)(kt & 3) * STAGE_B;
        const uint32_t bA = stg;
        const uint32_t bW = stg + MAT_B;

        #pragma unroll
        for (int h = 0; h < 4; h++) {
            const int kc = h * 16;
            uint32_t a[2][4];
            #pragma unroll
            for (int mi = 0; mi < 2; mi++) {
                const uint32_t off = (uint32_t)((rowA + mi * 16) * SROW + kc + colA) * 2;
                ldsm_x4(a[mi], bA + off);
            }
            uint32_t b[2][4];
            #pragma unroll
            for (int j = 0; j < 2; j++) {
                const uint32_t off = (uint32_t)((rowB + j * 16) * SROW + kc + colB) * 2;
                ldsm_x4(b[j], bW + off);
            }
            #pragma unroll
            for (int mi = 0; mi < 2; mi++)
                #pragma unroll
                for (int nj = 0; nj < 4; nj++) {
                    const int jj = nj >> 1, pp = (nj & 1) * 2;
                    mma16816h(acc[mi][nj], a[mi], b[jj][pp], b[jj][pp + 1]);
                }
        }
    }

    // epilogue: bias + tanh -> fp32 C and fp16 Ch
    const int r0l = lane >> 2;
    const int c0l = 2 * (lane & 3);
    #pragma unroll
    for (int mi = 0; mi < 2; mi++) {
        #pragma unroll
        for (int nj = 0; nj < 4; nj++) {
            const int gnl = N0 + nj * 8 + c0l;
            const float b0 = biasS[gnl], b1 = biasS[gnl + 1];
            const int gm0 = m0 + M0 + mi * 16 + r0l;
            float v00 = tanhf(acc[mi][nj][0] + b0);
            float v01 = tanhf(acc[mi][nj][1] + b1);
            float v10 = tanhf(acc[mi][nj][2] + b0);
            float v11 = tanhf(acc[mi][nj][3] + b1);
            float* p0 = C + (size_t)gm0 * DIM + n0 + gnl;
            float* p1 = p0 + (size_t)8 * DIM;
            *(float2*)p0 = make_float2(v00, v01);
            *(float2*)p1 = make_float2(v10, v11);
            if (Ch != nullptr) {
                *(__half2*)(Ch + (size_t)gm0 * DIM + n0 + gnl) =
                    __floats2half2_rn(v00, v01);
                *(__half2*)(Ch + (size_t)(gm0 + 8) * DIM + n0 + gnl) =
                    __floats2half2_rn(v10, v11);
            }
        }
    }
}

// ---------------------------------------------------------------------------
// 5) Fidelity dots (deterministic 2-stage reduction)
// ---------------------------------------------------------------------------
__global__ void fid_kernel(const float* __restrict__ a1, const float* __restrict__ a2,
                           const float* __restrict__ a3, const float* __restrict__ a4) {
    double s[10];
    #pragma unroll
    for (int k = 0; k < 10; k++) s[k] = 0.0;
    const int stride = gridDim.x * blockDim.x;
    for (int idx = blockIdx.x * blockDim.x + threadIdx.x; idx < OUTN; idx += stride) {
        double v1 = (double)a1[idx], v2 = (double)a2[idx];
        double v3 = (double)a3[idx], v4 = (double)a4[idx];
        s[0] += v1 * v1; s[1] += v1 * v2; s[2] += v1 * v3; s[3] += v1 * v4;
        s[4] += v2 * v2; s[5] += v2 * v3; s[6] += v2 * v4;
        s[7] += v3 * v3; s[8] += v3 * v4;
        s[9] += v4 * v4;
    }
    #pragma unroll
    for (int k = 0; k < 10; k++)
        #pragma unroll
        for (int off = 16; off > 0; off >>= 1)
            s[k] += __shfl_down_sync(0xFFFFFFFFu, s[k], off);
    __shared__ double ws[8][10];
    const int wid = threadIdx.x >> 5, lid = threadIdx.x & 31;
    if (lid == 0)
        #pragma unroll
        for (int k = 0; k < 10; k++) ws[wid][k] = s[k];
    __syncthreads();
    if (threadIdx.x == 0) {
        #pragma unroll
        for (int k = 0; k < 10; k++) {
            double acc = 0.0;
            for (int w = 0; w < 8; w++) acc += ws[w][k];
            g_partials[blockIdx.x * 10 + k] = acc;
        }
    }
}

__global__ void finalize_kernel(float* __restrict__ wout) {
    __shared__ double dots[10];
    const int t = threadIdx.x;
    const int w = t >> 5, lid = t & 31;
    if (w < 10) {
        double acc = 0.0;
        for (int p = lid; p < FID_BLOCKS; p += 32) acc += g_partials[p * 10 + w];
        #pragma unroll
        for (int off = 16; off > 0; off >>= 1)
            acc += __shfl_down_sync(0xFFFFFFFFu, acc, off);
        if (lid == 0) dots[w] = acc;
    }
    __syncthreads();
    if (t < 16) {
        int i = t >> 2, j = t & 3;
        int ii = i < j ? i : j, jj = i < j ? j : i;
        const int base[4] = {0, 4, 7, 9};
        double dij = dots[base[ii] + (jj - ii)];
        double dii = dots[base[ii]];
        double djj = dots[base[jj]];
        double ni = sqrt(dii) + 1e-12;
        double nj = sqrt(djj) + 1e-12;
        double sh = dij / (ni * nj);
        double fid = sh * sh;
        wout[t] = (fid >= 0.8 && i != j) ? 1.0f : 0.0f;
    }
}

// ---------------------------------------------------------------------------
// kernel_launch
// ---------------------------------------------------------------------------
extern "C" void kernel_launch(void* const* d_in, const int* in_sizes, int n_in,
                              void* d_out, int out_size) {
    const float* x   = (const float*)d_in[0];
    const float* cw  = (const float*)d_in[1];
    const float* cb  = (const float*)d_in[2];
    const float* rot = (const float*)d_in[3];
    const float* ent = (const float*)d_in[4];
    const float* W1  = (const float*)d_in[5];
    const float* b1  = (const float*)d_in[6];
    const float* W2  = (const float*)d_in[7];
    const float* b2  = (const float*)d_in[8];
    const float* W3  = (const float*)d_in[9];
    const float* b3  = (const float*)d_in[10];
    const float* W4  = (const float*)d_in[11];
    const float* b4  = (const float*)d_in[12];
    float* out = (float*)d_out;

    float *gc, *ga, *ga1, *ga2, *ga3;
    __half *ah, *wh;
    cudaGetSymbolAddress((void**)&gc,  g_c);
    cudaGetSymbolAddress((void**)&ga,  g_a);
    cudaGetSymbolAddress((void**)&ga1, g_act1);
    cudaGetSymbolAddress((void**)&ga2, g_act2);
    cudaGetSymbolAddress((void**)&ga3, g_act3);
    cudaGetSymbolAddress((void**)&ah,  g_ah);
    cudaGetSymbolAddress((void**)&wh,  g_wh);

    cudaFuncSetAttribute(gemm_mma_kernel,
                         cudaFuncAttributeMaxDynamicSharedMemorySize, SMEM_REQ);

    const size_t WN = (size_t)DIM * KDIM;
    dim3 ggrid(DIM / 128, BB / 128);  // (32, 4)

    conv_kernel<<<BB, 256>>>(x, cw, cb, gc);                       // 0
    attn_kernel<<<1, BB>>>(gc, rot, ent, ga);                      // 1
    convert_w_kernel<<<(int)(WN / 1024), 256>>>(W2, wh + 0 * WN);  // 2
    layer1_kernel<<<OUTN / 256, 256>>>(ga, W1, b1, ga1,            // 3
                                       ah + 0 * (size_t)OUTN);
    convert_w_kernel<<<(int)(WN / 1024), 256>>>(W3, wh + 1 * WN);  // 4
    gemm_mma_kernel<<<ggrid, 512, SMEM_REQ>>>(                     // 5
        ah + 0 * (size_t)OUTN, wh + 0 * WN, b2, ga2,
        ah + 1 * (size_t)OUTN);
    convert_w_kernel<<<(int)(WN / 1024), 256>>>(W4, wh + 2 * WN);  // 6
    gemm_mma_kernel<<<ggrid, 512, SMEM_REQ>>>(                     // 7
        ah + 1 * (size_t)OUTN, wh + 1 * WN, b3, ga3,
        ah + 2 * (size_t)OUTN);
    gemm_mma_kernel<<<ggrid, 512, SMEM_REQ>>>(                     // 8
        ah + 2 * (size_t)OUTN, wh + 2 * WN, b4, out,
        nullptr);

    fid_kernel<<<FID_BLOCKS, 256>>>(ga1, ga2, ga3, out);           // 9
    finalize_kernel<<<1, 320>>>(out + OUTN);                       // 10
}

// round 7
// speedup vs baseline: 3.4686x; 1.0098x over previous
#include <cuda_runtime.h>
#include <cuda_bf16.h>
#include <cuda_fp16.h>
#include <math.h>
#include <stdint.h>

// ---------------------------------------------------------------------------
// Problem constants
// ---------------------------------------------------------------------------
#define BB   512
#define HH   128
#define WW   128
#define CONVN 16129
#define DIM  4096
#define KDIM 4096
#define OUTN (BB * DIM)

// ---------------------------------------------------------------------------
// Scratch (__device__ globals; no cudaMalloc allowed)
// ---------------------------------------------------------------------------
__device__ float g_c[BB];
__device__ float g_act1[OUTN];
__device__ float g_act2[OUTN];
__device__ float g_act3[OUTN];
__device__ __half g_ah[3][OUTN];
__device__ __half g_wh[3][DIM * KDIM];
#define FID_BLOCKS 512
__device__ double g_partials[FID_BLOCKS * 10];

// ---------------------------------------------------------------------------
// PTX helpers (plain-PTX, valid on non-'a' targets)
// ---------------------------------------------------------------------------
__device__ __forceinline__ uint32_t smem_to_u32(const void* p) {
    uint32_t a;
    asm("{ .reg .u64 t; cvta.to.shared.u64 t, %1; cvt.u32.u64 %0, t; }"
        : "=r"(a) : "l"(p));
    return a;
}
__device__ __forceinline__ void cpasync16(uint32_t dst, const void* gsrc) {
    asm volatile("cp.async.cg.shared.global [%0], [%1], 16;"
                 :: "r"(dst), "l"(__cvta_generic_to_global(gsrc)) : "memory");
}
#define CP_COMMIT() asm volatile("cp.async.commit_group;" ::: "memory")
template <int N>
__device__ __forceinline__ void cp_wait() {
    asm volatile("cp.async.wait_group %0;" :: "n"(N) : "memory");
}
__device__ __forceinline__ void ldsm_x4(uint32_t r[4], uint32_t addr) {
    asm volatile("ldmatrix.sync.aligned.m8n8.x4.shared.b16 {%0,%1,%2,%3}, [%4];"
                 : "=r"(r[0]), "=r"(r[1]), "=r"(r[2]), "=r"(r[3]) : "r"(addr));
}
__device__ __forceinline__ void mma16816h(float d[4], const uint32_t a[4],
                                          uint32_t b0, uint32_t b1) {
    asm volatile(
        "mma.sync.aligned.m16n8k16.row.col.f32.f16.f16.f32 "
        "{%0,%1,%2,%3}, {%4,%5,%6,%7}, {%8,%9}, {%0,%1,%2,%3};"
        : "+f"(d[0]), "+f"(d[1]), "+f"(d[2]), "+f"(d[3])
        : "r"(a[0]), "r"(a[1]), "r"(a[2]), "r"(a[3]), "r"(b0), "r"(b1));
}

// ---------------------------------------------------------------------------
// 1) Conv 2x2 valid + bias + sigmoid + mean -> g_c[n]
// ---------------------------------------------------------------------------
__global__ void conv_kernel(const float* __restrict__ x,
                            const float* __restrict__ cw,
                            const float* __restrict__ cb,
                            float* __restrict__ cOut) {
    const int n = blockIdx.x;
    const float* xp = x + n * HH * WW;
    const float w00 = cw[0], w01 = cw[1], w10 = cw[2], w11 = cw[3];
    const float bias = cb[0];
    float s = 0.0f;
    for (int idx = threadIdx.x; idx < 127 * 32; idx += 256) {
        const int i = idx >> 5;
        const int j = (idx & 31) * 4;
        const float* r0 = xp + i * WW + j;
        const float* r1 = r0 + WW;
        float4 a = *(const float4*)r0;
        float4 b = *(const float4*)r1;
        float a4 = 0.0f, b4 = 0.0f;
        if (j + 4 < WW) { a4 = r0[4]; b4 = r1[4]; }
        float x0[5] = {a.x, a.y, a.z, a.w, a4};
        float x1[5] = {b.x, b.y, b.z, b.w, b4};
        #pragma unroll
        for (int k = 0; k < 4; k++) {
            if (j + k < 127) {
                float v = x0[k] * w00 + x0[k + 1] * w01
                        + x1[k] * w10 + x1[k + 1] * w11 + bias;
                s += 1.0f / (1.0f + __expf(-v));
            }
        }
    }
    __shared__ float red[256];
    red[threadIdx.x] = s;
    __syncthreads();
    #pragma unroll
    for (int off = 128; off > 0; off >>= 1) {
        if (threadIdx.x < off) red[threadIdx.x] += red[threadIdx.x + off];
        __syncthreads();
    }
    if (threadIdx.x == 0) cOut[n] = red[0] / (float)CONVN;
}

// ---------------------------------------------------------------------------
// 2) Fused attention + Layer 1.
//    Each block handles 256 columns of one row i: recomputes a[i] via a
//    block-wide reduction over c (deterministic fixed-order), then
//    act1[i,j] = tanh(a_i * W1[j] + b1[j]) -> fp32 + fp16.
// ---------------------------------------------------------------------------
__global__ void attn_layer1_kernel(const float* __restrict__ c,
                                   const float* __restrict__ rot,
                                   const float* __restrict__ ent,
                                   const float* __restrict__ W1,
                                   const float* __restrict__ b1,
                                   float* __restrict__ out,
                                   __half* __restrict__ oh) {
    const int idx = blockIdx.x * 256 + threadIdx.x;
    const int i = idx >> 12;            // row (constant per block)
    const int j = idx & (DIM - 1);
    const int t = threadIdx.x;

    __shared__ float cs[BB];
    __shared__ float wred[8][2];
    __shared__ float aI;

    cs[t] = c[t];
    cs[t + 256] = c[t + 256];
    __syncthreads();

    const float e = ent[0];
    const float qi = cs[i] * rot[0];

    // block reduce over 512 elems (2 per thread): max of qi*c_j*e, then sums
    float v0 = qi * cs[t] * e, v1 = qi * cs[t + 256] * e;
    float mx = fmaxf(v0, v1);
    #pragma unroll
    for (int off = 16; off > 0; off >>= 1)
        mx = fmaxf(mx, __shfl_xor_sync(0xFFFFFFFFu, mx, off));
    if ((t & 31) == 0) wred[t >> 5][0] = mx;
    __syncthreads();
    float m = wred[0][0];
    #pragma unroll
    for (int w = 1; w < 8; w++) m = fmaxf(m, wred[w][0]);

    float e0 = __expf(v0 - m), e1 = __expf(v1 - m);
    float se = e0 + e1;
    float sa = e0 * cs[t] + e1 * cs[t + 256];
    #pragma unroll
    for (int off = 16; off > 0; off >>= 1) {
        se += __shfl_xor_sync(0xFFFFFFFFu, se, off);
        sa += __shfl_xor_sync(0xFFFFFFFFu, sa, off);
    }
    if ((t & 31) == 0) { wred[t >> 5][0] = se; wred[t >> 5][1] = sa; }
    __syncthreads();
    if (t == 0) {
        float tse = 0.0f, tsa = 0.0f;
        #pragma unroll
        for (int w = 0; w < 8; w++) { tse += wred[w][0]; tsa += wred[w][1]; }
        aI = tsa / tse;
    }
    __syncthreads();

    float o = tanhf(fmaf(aI, W1[j], b1[j]));
    out[idx] = o;
    oh[idx] = __float2half(o);
}

// ---------------------------------------------------------------------------
// W -> fp16 conversion
// ---------------------------------------------------------------------------
__global__ void convert_w_kernel(const float* __restrict__ W,
                                 __half* __restrict__ hi) {
    int i = (blockIdx.x * 256 + threadIdx.x) * 4;
    float4 v = *(const float4*)(W + i);
    *(__half2*)(hi + i)     = __floats2half2_rn(v.x, v.y);
    *(__half2*)(hi + i + 2) = __floats2half2_rn(v.z, v.w);
}

// ---------------------------------------------------------------------------
// 3) HMMA GEMM + bias + tanh:
//    C[512,4096] = tanh(A @ W^T + b); A, W fp16, fp32 accum.
//    CTA 128x128, 16 warps (4x4), warp tile 32x32, KT=64, 4-stage cp.async,
//    h-loop double-buffered ldmatrix.
// ---------------------------------------------------------------------------
#define KT      64
#define NT      (KDIM / KT)           // 64
#define SROW    72                    // padded row stride in halves (144 B)
#define MAT_B   (128 * SROW * 2)      // 18432 B
#define NMAT    2
#define STAGE_B (NMAT * MAT_B)        // 36864 B
#define NSTAGE  4
#define BIAS_OFF (NSTAGE * STAGE_B)   // 147456
#define SMEM_REQ (BIAS_OFF + 512)

__global__ void __launch_bounds__(512, 1)
gemm_mma_kernel(const __half* __restrict__ Ah,
                const __half* __restrict__ Wh,
                const float* __restrict__ bias,
                float* __restrict__ C,
                __half* __restrict__ Ch) {
    extern __shared__ __align__(16) char smem[];
    const uint32_t sbase = smem_to_u32(smem);
    float* biasS = (float*)(smem + BIAS_OFF);

    const int t = threadIdx.x;
    const int lane = t & 31;
    const int warp = t >> 5;            // 0..15
    const int mw = warp >> 2;           // 0..3
    const int nw = warp & 3;            // 0..3
    const int M0 = mw * 32;
    const int N0 = nw * 32;
    const int m0 = blockIdx.y * 128;
    const int n0 = blockIdx.x * 128;

    if (t < 128) biasS[t] = bias[n0 + t];

    const __half* gbase[NMAT];
    gbase[0] = Ah + (size_t)m0 * KDIM;
    gbase[1] = Wh + (size_t)n0 * KDIM;

    #define ISSUE_STAGE(ktv, slot) do {                                        \
        const int _kt = (ktv);                                                 \
        const uint32_t _stg = sbase + (uint32_t)(slot) * STAGE_B;              \
        _Pragma("unroll")                                                      \
        for (int _i = 0; _i < 4; _i++) {                                       \
            const int _c = _i * 512 + t;                                       \
            const int _mat = _c >> 10;                                         \
            const int _w = _c & 1023;                                          \
            const int _r = _w >> 3;                                            \
            const int _c16 = _w & 7;                                           \
            cpasync16(_stg + (uint32_t)_mat * MAT_B                            \
                           + (uint32_t)(_r * SROW + _c16 * 8) * 2,             \
                      gbase[_mat] + (size_t)_r * KDIM + _kt * KT + _c16 * 8);  \
        }                                                                      \
    } while (0)

    ISSUE_STAGE(0, 0); CP_COMMIT();
    ISSUE_STAGE(1, 1); CP_COMMIT();
    ISSUE_STAGE(2, 2); CP_COMMIT();

    // ldmatrix lane addressing
    const int g = lane >> 3, rin = lane & 7;
    const int rowA = M0 + (g & 1) * 8 + rin;
    const int colA = (g >> 1) * 8;
    const int rowB = N0 + (g >> 1) * 8 + rin;
    const int colB = (g & 1) * 8;

    float acc[2][4][4];
    #pragma unroll
    for (int i = 0; i < 2; i++)
        #pragma unroll
        for (int j = 0; j < 4; j++)
            #pragma unroll
            for (int k = 0; k < 4; k++) acc[i][j][k] = 0.0f;

    uint32_t aF[2][2][4], bF[2][2][4];   // [buf][mi or j][frag]

    #define LOADH(hh, buf, bA, bW) do {                                        \
        const int _kc = (hh) * 16;                                             \
        _Pragma("unroll")                                                      \
        for (int _mi = 0; _mi < 2; _mi++)                                      \
            ldsm_x4(aF[buf][_mi],                                              \
                    (bA) + (uint32_t)((rowA + _mi * 16) * SROW + _kc + colA) * 2); \
        _Pragma("unroll")                                                      \
        for (int _j = 0; _j < 2; _j++)                                         \
            ldsm_x4(bF[buf][_j],                                               \
                    (bW) + (uint32_t)((rowB + _j * 16) * SROW + _kc + colB) * 2);  \
    } while (0)

    for (int kt = 0; kt < NT; kt++) {
        cp_wait<NSTAGE - 2>();
        __syncthreads();
        if (kt + NSTAGE - 1 < NT) ISSUE_STAGE(kt + NSTAGE - 1, (kt + NSTAGE - 1) & 3);
        CP_COMMIT();

        const uint32_t stg = sbase + (uint32_t)(kt & 3) * STAGE_B;
        const uint32_t bA = stg;
        const uint32_t bW = stg + MAT_B;

        LOADH(0, 0, bA, bW);
        #pragma unroll
        for (int h = 0; h < 4; h++) {
            const int cur = h & 1;
            if (h < 3) LOADH(h + 1, cur ^ 1, bA, bW);
            #pragma unroll
            for (int mi = 0; mi < 2; mi++)
                #pragma unroll
                for (int nj = 0; nj < 4; nj++) {
                    const int jj = nj >> 1, pp = (nj & 1) * 2;
                    mma16816h(acc[mi][nj], aF[cur][mi],
                              bF[cur][jj][pp], bF[cur][jj][pp + 1]);
                }
        }
    }

    // epilogue: bias + tanh -> fp32 C and fp16 Ch
    const int r0l = lane >> 2;
    const int c0l = 2 * (lane & 3);
    #pragma unroll
    for (int mi = 0; mi < 2; mi++) {
        #pragma unroll
        for (int nj = 0; nj < 4; nj++) {
            const int gnl = N0 + nj * 8 + c0l;
            const float b0 = biasS[gnl], b1 = biasS[gnl + 1];
            const int gm0 = m0 + M0 + mi * 16 + r0l;
            float v00 = tanhf(acc[mi][nj][0] + b0);
            float v01 = tanhf(acc[mi][nj][1] + b1);
            float v10 = tanhf(acc[mi][nj][2] + b0);
            float v11 = tanhf(acc[mi][nj][3] + b1);
            float* p0 = C + (size_t)gm0 * DIM + n0 + gnl;
            float* p1 = p0 + (size_t)8 * DIM;
            *(float2*)p0 = make_float2(v00, v01);
            *(float2*)p1 = make_float2(v10, v11);
            if (Ch != nullptr) {
                *(__half2*)(Ch + (size_t)gm0 * DIM + n0 + gnl) =
                    __floats2half2_rn(v00, v01);
                *(__half2*)(Ch + (size_t)(gm0 + 8) * DIM + n0 + gnl) =
                    __floats2half2_rn(v10, v11);
            }
        }
    }
}

// ---------------------------------------------------------------------------
// 4) Fidelity dots (deterministic 2-stage reduction)
// ---------------------------------------------------------------------------
__global__ void fid_kernel(const float* __restrict__ a1, const float* __restrict__ a2,
                           const float* __restrict__ a3, const float* __restrict__ a4) {
    double s[10];
    #pragma unroll
    for (int k = 0; k < 10; k++) s[k] = 0.0;
    const int stride = gridDim.x * blockDim.x;
    for (int idx = blockIdx.x * blockDim.x + threadIdx.x; idx < OUTN; idx += stride) {
        double v1 = (double)a1[idx], v2 = (double)a2[idx];
        double v3 = (double)a3[idx], v4 = (double)a4[idx];
        s[0] += v1 * v1; s[1] += v1 * v2; s[2] += v1 * v3; s[3] += v1 * v4;
        s[4] += v2 * v2; s[5] += v2 * v3; s[6] += v2 * v4;
        s[7] += v3 * v3; s[8] += v3 * v4;
        s[9] += v4 * v4;
    }
    #pragma unroll
    for (int k = 0; k < 10; k++)
        #pragma unroll
        for (int off = 16; off > 0; off >>= 1)
            s[k] += __shfl_down_sync(0xFFFFFFFFu, s[k], off);
    __shared__ double ws[8][10];
    const int wid = threadIdx.x >> 5, lid = threadIdx.x & 31;
    if (lid == 0)
        #pragma unroll
        for (int k = 0; k < 10; k++) ws[wid][k] = s[k];
    __syncthreads();
    if (threadIdx.x == 0) {
        #pragma unroll
        for (int k = 0; k < 10; k++) {
            double acc = 0.0;
            for (int w = 0; w < 8; w++) acc += ws[w][k];
            g_partials[blockIdx.x * 10 + k] = acc;
        }
    }
}

__global__ void finalize_kernel(float* __restrict__ wout) {
    __shared__ double dots[10];
    const int t = threadIdx.x;
    const int w = t >> 5, lid = t & 31;
    if (w < 10) {
        double acc = 0.0;
        for (int p = lid; p < FID_BLOCKS; p += 32) acc += g_partials[p * 10 + w];
        #pragma unroll
        for (int off = 16; off > 0; off >>= 1)
            acc += __shfl_down_sync(0xFFFFFFFFu, acc, off);
        if (lid == 0) dots[w] = acc;
    }
    __syncthreads();
    if (t < 16) {
        int i = t >> 2, j = t & 3;
        int ii = i < j ? i : j, jj = i < j ? j : i;
        const int base[4] = {0, 4, 7, 9};
        double dij = dots[base[ii] + (jj - ii)];
        double dii = dots[base[ii]];
        double djj = dots[base[jj]];
        double ni = sqrt(dii) + 1e-12;
        double nj = sqrt(djj) + 1e-12;
        double sh = dij / (ni * nj);
        double fid = sh * sh;
        wout[t] = (fid >= 0.8 && i != j) ? 1.0f : 0.0f;
    }
}

// ---------------------------------------------------------------------------
// kernel_launch  (gemm1 is the 4th launch -> gets profiled)
// ---------------------------------------------------------------------------
extern "C" void kernel_launch(void* const* d_in, const int* in_sizes, int n_in,
                              void* d_out, int out_size) {
    const float* x   = (const float*)d_in[0];
    const float* cw  = (const float*)d_in[1];
    const float* cb  = (const float*)d_in[2];
    const float* rot = (const float*)d_in[3];
    const float* ent = (const float*)d_in[4];
    const float* W1  = (const float*)d_in[5];
    const float* b1  = (const float*)d_in[6];
    const float* W2  = (const float*)d_in[7];
    const float* b2  = (const float*)d_in[8];
    const float* W3  = (const float*)d_in[9];
    const float* b3  = (const float*)d_in[10];
    const float* W4  = (const float*)d_in[11];
    const float* b4  = (const float*)d_in[12];
    float* out = (float*)d_out;

    float *gc, *ga1, *ga2, *ga3;
    __half *ah, *wh;
    cudaGetSymbolAddress((void**)&gc,  g_c);
    cudaGetSymbolAddress((void**)&ga1, g_act1);
    cudaGetSymbolAddress((void**)&ga2, g_act2);
    cudaGetSymbolAddress((void**)&ga3, g_act3);
    cudaGetSymbolAddress((void**)&ah,  g_ah);
    cudaGetSymbolAddress((void**)&wh,  g_wh);

    cudaFuncSetAttribute(gemm_mma_kernel,
                         cudaFuncAttributeMaxDynamicSharedMemorySize, SMEM_REQ);

    const size_t WN = (size_t)DIM * KDIM;
    dim3 ggrid(DIM / 128, BB / 128);  // (32, 4)

    conv_kernel<<<BB, 256>>>(x, cw, cb, gc);                         // 0
    convert_w_kernel<<<(int)(WN / 1024), 256>>>(W2, wh + 0 * WN);    // 1
    attn_layer1_kernel<<<OUTN / 256, 256>>>(gc, rot, ent, W1, b1,    // 2
                                            ga1, ah + 0 * (size_t)OUTN);
    gemm_mma_kernel<<<ggrid, 512, SMEM_REQ>>>(                       // 3 <- profiled
        ah + 0 * (size_t)OUTN, wh + 0 * WN, b2, ga2,
        ah + 1 * (size_t)OUTN);
    convert_w_kernel<<<(int)(WN / 1024), 256>>>(W3, wh + 1 * WN);    // 4
    gemm_mma_kernel<<<ggrid, 512, SMEM_REQ>>>(                       // 5
        ah + 1 * (size_t)OUTN, wh + 1 * WN, b3, ga3,
        ah + 2 * (size_t)OUTN);
    convert_w_kernel<<<(int)(WN / 1024), 256>>>(W4, wh + 2 * WN);    // 6
    gemm_mma_kernel<<<ggrid, 512, SMEM_REQ>>>(                       // 7
        ah + 2 * (size_t)OUTN, wh + 2 * WN, b4, out,
        nullptr);

    fid_kernel<<<FID_BLOCKS, 256>>>(ga1, ga2, ga3, out);             // 8
    finalize_kernel<<<1, 320>>>(out + OUTN);                         // 9
}